// round 3
// baseline (speedup 1.0000x reference)
#include <cuda_runtime.h>
#include <math.h>

// Problem constants: B=4, C=256, Fq=64, T=256, HEADS=8, Dh=32, GROUPS=32, WIN=16
#define NTOK   65536        // B*Fq*T tokens
#define ELEMS  16777216     // NTOK * 256

// ---------------- scratch (device globals; no allocation allowed) ----------------
__device__ float g_x[ELEMS];        // running activation, NHWC token-major [p, c]
__device__ float g_h[ELEMS];
__device__ float g_h2[ELEMS];
__device__ float g_y[ELEMS];
__device__ float g_qkv[3*ELEMS];    // [NTOK, 768]
__device__ float g_a3[65536];       // layer3 attn out [B*Fq, C]
__device__ float g_a3b[65536];      // after out3 GEMM
__device__ float g_wt[589824];      // transposed conv weights [k=(ky,kx,ci)][co]

// ---------------- transposes ----------------
// in: NCHW x[b][c][fq][t]  -> out: NHWC [ (b*64+fq)*256+t , c ]
__global__ void k_nchw_to_nhwc(const float* __restrict__ in, float* __restrict__ out) {
    __shared__ float tile[32][33];
    int bfq = blockIdx.z, b = bfq >> 6, fq = bfq & 63;
    int t0 = blockIdx.x * 32, c0 = blockIdx.y * 32;
    for (int r = threadIdx.y; r < 32; r += 8)
        tile[r][threadIdx.x] = in[(((size_t)b*256 + c0 + r)*64 + fq)*256 + t0 + threadIdx.x];
    __syncthreads();
    for (int r = threadIdx.y; r < 32; r += 8)
        out[((size_t)bfq*256 + t0 + r)*256 + c0 + threadIdx.x] = tile[threadIdx.x][r];
}

// out[b][c][fq][t] = xa[p,c] + xb[p,c]   (final residual + output transpose)
__global__ void k_nhwc_to_nchw_add(const float* __restrict__ xa, const float* __restrict__ xb,
                                   float* __restrict__ out) {
    __shared__ float tile[32][33];
    int bfq = blockIdx.z, b = bfq >> 6, fq = bfq & 63;
    int t0 = blockIdx.x * 32, c0 = blockIdx.y * 32;
    for (int r = threadIdx.y; r < 32; r += 8) {
        size_t p = ((size_t)bfq*256 + t0 + r)*256 + c0 + threadIdx.x;
        tile[r][threadIdx.x] = xa[p] + xb[p];
    }
    __syncthreads();
    for (int r = threadIdx.y; r < 32; r += 8)
        out[(((size_t)b*256 + c0 + r)*64 + fq)*256 + t0 + threadIdx.x] = tile[threadIdx.x][r];
}

// conv weight transpose: wt[(kyx*256+ci)*256 + co] = w[co*2304 + ci*9 + kyx]
// (conv gemm decodes k as kyx = k>>8, ci = k&255; OIHW inner order is ci*9+kyx)
__global__ void k_wtrans(const float* __restrict__ w, float* __restrict__ wt) {
    int idx = blockIdx.x * 256 + threadIdx.x;   // grid 2304 -> 589824 elems
    int co = idx & 255, k = idx >> 8;           // k = kyx*256 + ci
    int kyx = k >> 8, ci = k & 255;
    wt[idx] = w[(size_t)co * 2304 + ci * 9 + kyx];
}

// ---------------- GroupNorm over (c-in-group, Fq, T) per (b, g)  [NHWC] ----------------
__global__ void k_gn_bg(const float* __restrict__ in, float* __restrict__ out, float eps) {
    __shared__ float rs[64];
    int b = blockIdx.x >> 5, g = blockIdx.x & 31;
    const float* base = in  + (size_t)b*16384*256 + g*8;
    float*       ob   = out + (size_t)b*16384*256 + g*8;
    float s = 0.f, s2 = 0.f;
    for (int i = threadIdx.x; i < 16384; i += 256) {
        const float4* r = (const float4*)(base + (size_t)i*256);
        float4 a = r[0], c = r[1];
        s  += a.x+a.y+a.z+a.w + c.x+c.y+c.z+c.w;
        s2 += a.x*a.x+a.y*a.y+a.z*a.z+a.w*a.w + c.x*c.x+c.y*c.y+c.z*c.z+c.w*c.w;
    }
    int lane = threadIdx.x & 31, w = threadIdx.x >> 5;
    #pragma unroll
    for (int o = 16; o; o >>= 1) {
        s  += __shfl_down_sync(0xffffffffu, s,  o);
        s2 += __shfl_down_sync(0xffffffffu, s2, o);
    }
    if (lane == 0) { rs[w] = s; rs[32 + w] = s2; }
    __syncthreads();
    if (threadIdx.x == 0) {
        float S = 0.f, S2 = 0.f;
        for (int i = 0; i < 8; i++) { S += rs[i]; S2 += rs[32 + i]; }
        rs[0] = S; rs[32] = S2;
    }
    __syncthreads();
    float mean = rs[0] * (1.f/131072.f);
    float var  = rs[32] * (1.f/131072.f) - mean*mean;
    float inv  = rsqrtf(var + eps);
    for (int i = threadIdx.x; i < 16384; i += 256) {
        const float4* r = (const float4*)(base + (size_t)i*256);
        float4 a = r[0], c = r[1];
        a.x = (a.x-mean)*inv; a.y = (a.y-mean)*inv; a.z = (a.z-mean)*inv; a.w = (a.w-mean)*inv;
        c.x = (c.x-mean)*inv; c.y = (c.y-mean)*inv; c.z = (c.z-mean)*inv; c.w = (c.w-mean)*inv;
        float4* o4 = (float4*)(ob + (size_t)i*256);
        o4[0] = a; o4[1] = c;
    }
}

// ---------------- SGEMM 128x128x8, 256 threads, 8x8 micro ----------------
template<bool BIAS>
__global__ void k_sgemm(const float* __restrict__ A, const float* __restrict__ B,
                        const float* __restrict__ bias, float* __restrict__ Cout,
                        int M, int N, int K) {
    __shared__ float As[8][128];
    __shared__ float Bs[8][128];
    int tid = threadIdx.x;
    int bn = blockIdx.x * 128, bm = blockIdx.y * 128;
    int arow = tid >> 1, acol = (tid & 1) << 2;
    int brow = tid >> 5, bcol = (tid & 31) << 2;
    int ty = tid >> 4, tx = tid & 15;
    float acc[8][8] = {};
    const float* Ap = A + (size_t)(bm + arow) * K + acol;
    const float* Bp = B + (size_t)brow * N + bn + bcol;
    for (int k0 = 0; k0 < K; k0 += 8) {
        float4 av = *(const float4*)(Ap + k0);
        float4 bv = *(const float4*)(Bp + (size_t)k0 * N);
        As[acol+0][arow] = av.x; As[acol+1][arow] = av.y;
        As[acol+2][arow] = av.z; As[acol+3][arow] = av.w;
        *(float4*)&Bs[brow][bcol] = bv;
        __syncthreads();
        #pragma unroll
        for (int k = 0; k < 8; k++) {
            float ar[8], br[8];
            *(float4*)(ar)   = *(const float4*)&As[k][ty*8];
            *(float4*)(ar+4) = *(const float4*)&As[k][ty*8+4];
            *(float4*)(br)   = *(const float4*)&Bs[k][tx*8];
            *(float4*)(br+4) = *(const float4*)&Bs[k][tx*8+4];
            #pragma unroll
            for (int i = 0; i < 8; i++)
                #pragma unroll
                for (int j = 0; j < 8; j++)
                    acc[i][j] += ar[i] * br[j];
        }
        __syncthreads();
    }
    #pragma unroll
    for (int i = 0; i < 8; i++) {
        size_t row = bm + ty*8 + i;
        #pragma unroll
        for (int j = 0; j < 8; j++) {
            int col = bn + tx*8 + j;
            float v = acc[i][j];
            if (BIAS) v += bias[col];
            Cout[row * N + col] = v;
        }
    }
}

// ---------------- conv3x3 as implicit GEMM (NHWC), K = 9*256 ordered (ky,kx,ci) ------
// MODE 1: +bias +gate_diff*temb, then SiLU (conv1).  MODE 0: plain (conv2).
template<int MODE>
__global__ void k_conv_gemm(const float* __restrict__ In, const float* __restrict__ Wt,
                            const float* __restrict__ bias, const float* __restrict__ temb,
                            const float* __restrict__ gate, float* __restrict__ Out) {
    __shared__ float As[8][128];
    __shared__ float Bs[8][128];
    int tid = threadIdx.x;
    int bn = blockIdx.x * 128, bm = blockIdx.y * 128;
    int arow = tid >> 1, acol = (tid & 1) << 2;
    int brow = tid >> 5, bcol = (tid & 31) << 2;
    int ty = tid >> 4, tx = tid & 15;
    int p = bm + arow;
    int b = p >> 14, rem = p & 16383, fy = rem >> 8, fx = rem & 255;
    float acc[8][8] = {};
    const float* Bp = Wt + (size_t)brow * 256 + bn + bcol;
    for (int k0 = 0; k0 < 2304; k0 += 8) {
        int ka  = k0 + acol;
        int kyx = ka >> 8, ci = ka & 255;
        int ky = kyx / 3, kx = kyx - ky * 3;
        int fy2 = fy + ky - 1, fx2 = fx + kx - 1;
        float4 av = make_float4(0.f, 0.f, 0.f, 0.f);
        if ((unsigned)fy2 < 64u && (unsigned)fx2 < 256u)
            av = *(const float4*)(In + (((size_t)(b*64 + fy2))*256 + fx2)*256 + ci);
        As[acol+0][arow] = av.x; As[acol+1][arow] = av.y;
        As[acol+2][arow] = av.z; As[acol+3][arow] = av.w;
        *(float4*)&Bs[brow][bcol] = *(const float4*)(Bp + (size_t)k0 * 256);
        __syncthreads();
        #pragma unroll
        for (int k = 0; k < 8; k++) {
            float ar[8], br[8];
            *(float4*)(ar)   = *(const float4*)&As[k][ty*8];
            *(float4*)(ar+4) = *(const float4*)&As[k][ty*8+4];
            *(float4*)(br)   = *(const float4*)&Bs[k][tx*8];
            *(float4*)(br+4) = *(const float4*)&Bs[k][tx*8+4];
            #pragma unroll
            for (int i = 0; i < 8; i++)
                #pragma unroll
                for (int j = 0; j < 8; j++)
                    acc[i][j] += ar[i] * br[j];
        }
        __syncthreads();
    }
    float gd = (MODE == 1) ? gate[0] : 0.f;
    #pragma unroll
    for (int i = 0; i < 8; i++) {
        int row = bm + ty*8 + i;
        #pragma unroll
        for (int j = 0; j < 8; j++) {
            int co = bn + tx*8 + j;
            float v = acc[i][j];
            if (MODE == 1) {
                v += bias[co] + gd * temb[(row >> 14)*256 + co];
                v = v / (1.f + __expf(-v));           // SiLU
            }
            Out[(size_t)row * 256 + co] = v;
        }
    }
}

// ---------------- elementwise: x += gate * h ----------------
__global__ void k_axpy_gate(float* __restrict__ x, const float* __restrict__ h,
                            const float* __restrict__ gate) {
    size_t i = ((size_t)blockIdx.x * 256 + threadIdx.x) * 4;
    float g = gate[0];
    float4 xv = *(float4*)(x + i);
    float4 hv = *(const float4*)(h + i);
    xv.x += g*hv.x; xv.y += g*hv.y; xv.z += g*hv.z; xv.w += g*hv.w;
    *(float4*)(x + i) = xv;
}

// ---------------- layer2 attention over Fq (seq 64) per (b,t,h) ----------------
__global__ void k_attn_freq(const float* __restrict__ qkv, float* __restrict__ y) {
    __shared__ float q[64][33], kk[64][33], v[64][33];
    __shared__ float S[64][65];
    int bt = blockIdx.x, h = blockIdx.y;
    int b = bt >> 8, t = bt & 255;
    int tid = threadIdx.x;
    for (int i = tid; i < 2048; i += 128) {
        int fq = i >> 5, d = i & 31;
        size_t base = ((size_t)((b*64 + fq)*256 + t))*768 + h*32 + d;
        q[fq][d]  = qkv[base];
        kk[fq][d] = qkv[base + 256];
        v[fq][d]  = qkv[base + 512];
    }
    __syncthreads();
    const float scale = 0.17677669529663687f;  // 1/sqrt(32)
    for (int i = tid; i < 4096; i += 128) {
        int L = i >> 6, l = i & 63;
        float s = 0.f;
        #pragma unroll
        for (int d = 0; d < 32; d++) s += q[L][d] * kk[l][d];
        S[L][l] = s * scale;
    }
    __syncthreads();
    if (tid < 64) {
        float m = -1e30f;
        for (int l = 0; l < 64; l++) m = fmaxf(m, S[tid][l]);
        float su = 0.f;
        for (int l = 0; l < 64; l++) { float e = __expf(S[tid][l] - m); S[tid][l] = e; su += e; }
        float r = 1.f / su;
        for (int l = 0; l < 64; l++) S[tid][l] *= r;
    }
    __syncthreads();
    for (int i = tid; i < 2048; i += 128) {
        int L = i >> 5, d = i & 31;
        float s = 0.f;
        #pragma unroll
        for (int l = 0; l < 64; l++) s += S[L][l] * v[l][d];
        y[((size_t)((b*64 + L)*256 + t))*256 + h*32 + d] = s;
    }
}

// ---------------- per-token GroupNorm(rowwise, 8 per group) then x += g2 * y ----------
__global__ void k_gnrow_add(const float* __restrict__ yv, float* __restrict__ x,
                            const float* __restrict__ gate) {
    int idx = blockIdx.x * 256 + threadIdx.x;          // NTOK*32 total
    int p = idx >> 5, g = idx & 31;
    size_t off = (size_t)p * 256 + g * 8;
    float4 a = *(const float4*)(yv + off), c = *(const float4*)(yv + off + 4);
    float vals[8] = {a.x, a.y, a.z, a.w, c.x, c.y, c.z, c.w};
    float m = 0.f;
    #pragma unroll
    for (int j = 0; j < 8; j++) m += vals[j];
    m *= 0.125f;
    float var = 0.f;
    #pragma unroll
    for (int j = 0; j < 8; j++) { float dd = vals[j] - m; var += dd * dd; }
    var *= 0.125f;
    float inv = rsqrtf(var + 1e-5f);
    float gg = gate[0];
    float4 xa = *(float4*)(x + off), xb = *(float4*)(x + off + 4);
    xa.x += gg*(vals[0]-m)*inv; xa.y += gg*(vals[1]-m)*inv;
    xa.z += gg*(vals[2]-m)*inv; xa.w += gg*(vals[3]-m)*inv;
    xb.x += gg*(vals[4]-m)*inv; xb.y += gg*(vals[5]-m)*inv;
    xb.z += gg*(vals[6]-m)*inv; xb.w += gg*(vals[7]-m)*inv;
    *(float4*)(x + off) = xa; *(float4*)(x + off + 4) = xb;
}

// ---------------- layer3 global attention over T (mean-query) per (bfq, h) ----------
__global__ void k_attn_time(const float* __restrict__ qkv, float* __restrict__ yout) {
    __shared__ float part[8][32];
    __shared__ float qm[32];
    __shared__ float prob[256];
    __shared__ float redm[8], reds[8];
    int bfq = blockIdx.x, h = blockIdx.y;
    int tid = threadIdx.x;
    size_t tokbase = (size_t)bfq * 256;
    int d = tid & 31, grp = tid >> 5;
    float s = 0.f;
    for (int t = grp; t < 256; t += 8)
        s += qkv[(tokbase + t)*768 + h*32 + d];
    part[grp][d] = s;
    __syncthreads();
    if (tid < 32) {
        float ss = 0.f;
        #pragma unroll
        for (int g = 0; g < 8; g++) ss += part[g][tid];
        qm[tid] = ss * (1.f/256.f);
    }
    __syncthreads();
    const float* kr = qkv + (tokbase + tid)*768 + 256 + h*32;
    float sc = 0.f;
    #pragma unroll
    for (int dd = 0; dd < 32; dd++) sc += qm[dd] * kr[dd];
    sc *= 0.17677669529663687f;
    float m = sc;
    #pragma unroll
    for (int o = 16; o; o >>= 1) m = fmaxf(m, __shfl_xor_sync(0xffffffffu, m, o));
    if ((tid & 31) == 0) redm[grp] = m;
    __syncthreads();
    float M = redm[0];
    #pragma unroll
    for (int g = 1; g < 8; g++) M = fmaxf(M, redm[g]);
    float e = __expf(sc - M);
    float su = e;
    #pragma unroll
    for (int o = 16; o; o >>= 1) su += __shfl_xor_sync(0xffffffffu, su, o);
    if ((tid & 31) == 0) reds[grp] = su;
    __syncthreads();
    float Ssum = 0.f;
    #pragma unroll
    for (int g = 0; g < 8; g++) Ssum += reds[g];
    prob[tid] = e / Ssum;
    __syncthreads();
    float acc = 0.f;
    for (int t = grp; t < 256; t += 8)
        acc += prob[t] * qkv[(tokbase + t)*768 + 512 + h*32 + d];
    part[grp][d] = acc;
    __syncthreads();
    if (tid < 32) {
        float ss = 0.f;
        #pragma unroll
        for (int g = 0; g < 8; g++) ss += part[g][tid];
        yout[(size_t)bfq*256 + h*32 + tid] = ss;
    }
}

// ---------------- layer3 epilogue: per-row GN then broadcast add over T -------------
__global__ void k_gn_bcast_add(const float* __restrict__ yv, float* __restrict__ x,
                               const float* __restrict__ gate) {
    __shared__ float yn[256];
    int bfq = blockIdx.x, tid = threadIdx.x;
    if (tid < 32) {
        const float* r = yv + bfq*256 + tid*8;
        float vals[8];
        #pragma unroll
        for (int j = 0; j < 8; j++) vals[j] = r[j];
        float m = 0.f;
        #pragma unroll
        for (int j = 0; j < 8; j++) m += vals[j];
        m *= 0.125f;
        float var = 0.f;
        #pragma unroll
        for (int j = 0; j < 8; j++) { float dd = vals[j] - m; var += dd * dd; }
        var *= 0.125f;
        float inv = rsqrtf(var + 1e-5f);
        #pragma unroll
        for (int j = 0; j < 8; j++) yn[tid*8 + j] = (vals[j] - m) * inv;
    }
    __syncthreads();
    float add = gate[0] * yn[tid];
    float* xp = x + (size_t)bfq * 65536 + tid;
    for (int t = 0; t < 256; t++) xp[(size_t)t * 256] += add;
}

// ---------------- layer4 LSA: windows of 16 along T, per (bfq, w), loop heads -------
__global__ void k_attn_lsa(const float* __restrict__ qkv, float* __restrict__ y) {
    __shared__ float q[16][33], kk[16][33], v[16][33];
    __shared__ float S[16][17];
    int blk = blockIdx.x;
    size_t p0 = (size_t)(blk >> 4) * 256 + (blk & 15) * 16;
    int tid = threadIdx.x;
    int qi = tid >> 4, kj = tid & 15;
    const float scale = 0.17677669529663687f;
    for (int h = 0; h < 8; h++) {
        for (int i = tid; i < 512; i += 256) {
            int r = i >> 5, d = i & 31;
            size_t a = (p0 + r)*768 + h*32 + d;
            q[r][d] = qkv[a]; kk[r][d] = qkv[a + 256]; v[r][d] = qkv[a + 512];
        }
        __syncthreads();
        float s = 0.f;
        #pragma unroll
        for (int d = 0; d < 32; d++) s += q[qi][d] * kk[kj][d];
        S[qi][kj] = s * scale;
        __syncthreads();
        if (tid < 16) {
            float m = -1e30f;
            for (int j = 0; j < 16; j++) m = fmaxf(m, S[tid][j]);
            float su = 0.f;
            for (int j = 0; j < 16; j++) { float e = __expf(S[tid][j] - m); S[tid][j] = e; su += e; }
            float r = 1.f / su;
            for (int j = 0; j < 16; j++) S[tid][j] *= r;
        }
        __syncthreads();
        for (int i = tid; i < 512; i += 256) {
            int r = i >> 5, d = i & 31;
            float s2 = 0.f;
            #pragma unroll
            for (int j = 0; j < 16; j++) s2 += S[r][j] * v[j][d];
            y[(p0 + r)*256 + h*32 + d] = s2;
        }
        __syncthreads();
    }
}

// =====================================================================================
extern "C" void kernel_launch(void* const* d_in, const int* in_sizes, int n_in,
                              void* d_out, int out_size) {
    const float* x     = (const float*)d_in[0];
    const float* temb  = (const float*)d_in[1];
    const float* w1    = (const float*)d_in[2];
    const float* b1    = (const float*)d_in[3];
    const float* w2    = (const float*)d_in[4];
    const float* gdiff = (const float*)d_in[5];
    const float* gres  = (const float*)d_in[6];
    const float* g2    = (const float*)d_in[7];
    const float* g3    = (const float*)d_in[8];
    const float* qkv2w = (const float*)d_in[9];
    const float* qkv2b = (const float*)d_in[10];
    const float* out2w = (const float*)d_in[11];
    const float* qkv3w = (const float*)d_in[12];
    const float* qkv3b = (const float*)d_in[13];
    const float* out3w = (const float*)d_in[14];
    const float* lsaqw = (const float*)d_in[15];
    const float* lsaow = (const float*)d_in[16];
    float* out = (float*)d_out;

    float *px, *ph, *ph2, *py, *pqkv, *pa3, *pa3b, *pwt;
    cudaGetSymbolAddress((void**)&px,   g_x);
    cudaGetSymbolAddress((void**)&ph,   g_h);
    cudaGetSymbolAddress((void**)&ph2,  g_h2);
    cudaGetSymbolAddress((void**)&py,   g_y);
    cudaGetSymbolAddress((void**)&pqkv, g_qkv);
    cudaGetSymbolAddress((void**)&pa3,  g_a3);
    cudaGetSymbolAddress((void**)&pa3b, g_a3b);
    cudaGetSymbolAddress((void**)&pwt,  g_wt);

    dim3 tb32(32, 8);

    // ---- layout: NCHW -> NHWC token-major ----
    k_nchw_to_nhwc<<<dim3(8, 8, 256), tb32>>>(x, px);

    // ---- Residual block ----
    k_gn_bg<<<128, 256>>>(px, ph, 1e-6f);
    k_wtrans<<<2304, 256>>>(w1, pwt);
    k_conv_gemm<1><<<dim3(2, 512), 256>>>(ph, pwt, b1, temb, gdiff, ph2);
    k_gn_bg<<<128, 256>>>(ph2, ph, 1e-6f);
    k_wtrans<<<2304, 256>>>(w2, pwt);
    k_conv_gemm<0><<<dim3(2, 512), 256>>>(ph, pwt, nullptr, nullptr, nullptr, ph2);
    k_gn_bg<<<128, 256>>>(ph2, ph, 1e-6f);
    k_axpy_gate<<<16384, 256>>>(px, ph, gres);

    // ---- layer2: frequency self-attention ----
    k_sgemm<true><<<dim3(6, 512), 256>>>(px, qkv2w, qkv2b, pqkv, NTOK, 768, 256);
    k_attn_freq<<<dim3(1024, 8), 128>>>(pqkv, py);
    k_sgemm<false><<<dim3(2, 512), 256>>>(py, out2w, nullptr, ph, NTOK, 256, 256);
    k_gnrow_add<<<8192, 256>>>(ph, px, g2);

    // ---- layer3: global time attention ----
    k_sgemm<true><<<dim3(6, 512), 256>>>(px, qkv3w, qkv3b, pqkv, NTOK, 768, 256);
    k_attn_time<<<dim3(256, 8), 256>>>(pqkv, pa3);
    k_sgemm<false><<<dim3(2, 2), 256>>>(pa3, out3w, nullptr, pa3b, 256, 256, 256);
    k_gn_bcast_add<<<256, 256>>>(pa3b, px, g3);

    // ---- layer4: LSA ----
    k_gn_bg<<<128, 256>>>(px, ph, 1e-5f);
    k_sgemm<false><<<dim3(6, 512), 256>>>(ph, lsaqw, nullptr, pqkv, NTOK, 768, 256);
    k_attn_lsa<<<4096, 256>>>(pqkv, py);
    k_sgemm<false><<<dim3(2, 512), 256>>>(py, lsaow, nullptr, ph, NTOK, 256, 256);

    // ---- final residual + NHWC -> NCHW output ----
    k_nhwc_to_nchw_add<<<dim3(8, 8, 256), tb32>>>(px, ph, out);
}

// round 5
// speedup vs baseline: 2.4216x; 2.4216x over previous
#include <cuda_runtime.h>
#include <cstdint>
#include <math.h>

// Problem constants: B=4, C=256, Fq=64, T=256, HEADS=8, Dh=32, GROUPS=32, WIN=16
#define NTOK   65536
#define ELEMS  16777216

// ---------------- scratch ----------------
__device__ float g_x[ELEMS];
__device__ float g_h[ELEMS];
__device__ float g_h2[ELEMS];
__device__ float g_y[ELEMS];
__device__ float g_qkv[3*ELEMS];
__device__ float g_a3[65536];
__device__ float g_a3b[65536];
__device__ float g_wt[589824];      // [k=(kyx*256+ci)][co]

// ---------------- tf32 helpers ----------------
__device__ __forceinline__ uint32_t f2tf(float x) {
    uint32_t r; asm("cvt.rna.tf32.f32 %0, %1;" : "=r"(r) : "f"(x)); return r;
}
__device__ __forceinline__ void mma8(float* d, const uint32_t* a, const uint32_t* b) {
    asm volatile("mma.sync.aligned.m16n8k8.row.col.f32.tf32.tf32.f32 "
        "{%0,%1,%2,%3}, {%4,%5,%6,%7}, {%8,%9}, {%0,%1,%2,%3};"
        : "+f"(d[0]), "+f"(d[1]), "+f"(d[2]), "+f"(d[3])
        : "r"(a[0]), "r"(a[1]), "r"(a[2]), "r"(a[3]), "r"(b[0]), "r"(b[1]));
}

// ---------------- transposes ----------------
__global__ void k_nchw_to_nhwc(const float* __restrict__ in, float* __restrict__ out) {
    __shared__ float tile[32][33];
    int bfq = blockIdx.z, b = bfq >> 6, fq = bfq & 63;
    int t0 = blockIdx.x * 32, c0 = blockIdx.y * 32;
    for (int r = threadIdx.y; r < 32; r += 8)
        tile[r][threadIdx.x] = in[(((size_t)b*256 + c0 + r)*64 + fq)*256 + t0 + threadIdx.x];
    __syncthreads();
    for (int r = threadIdx.y; r < 32; r += 8)
        out[((size_t)bfq*256 + t0 + r)*256 + c0 + threadIdx.x] = tile[threadIdx.x][r];
}

__global__ void k_nhwc_to_nchw_add(const float* __restrict__ xa, const float* __restrict__ xb,
                                   float* __restrict__ out) {
    __shared__ float tile[32][33];
    int bfq = blockIdx.z, b = bfq >> 6, fq = bfq & 63;
    int t0 = blockIdx.x * 32, c0 = blockIdx.y * 32;
    for (int r = threadIdx.y; r < 32; r += 8) {
        size_t p = ((size_t)bfq*256 + t0 + r)*256 + c0 + threadIdx.x;
        tile[r][threadIdx.x] = xa[p] + xb[p];
    }
    __syncthreads();
    for (int r = threadIdx.y; r < 32; r += 8)
        out[(((size_t)b*256 + c0 + r)*64 + fq)*256 + t0 + threadIdx.x] = tile[threadIdx.x][r];
}

// wt[(kyx*256+ci)*256 + co] = w[co*2304 + ci*9 + kyx]
__global__ void k_wtrans(const float* __restrict__ w, float* __restrict__ wt) {
    int idx = blockIdx.x * 256 + threadIdx.x;
    int co = idx & 255, k = idx >> 8;
    int kyx = k >> 8, ci = k & 255;
    wt[idx] = w[(size_t)co * 2304 + ci * 9 + kyx];
}

// ---------------- GroupNorm per (b, g) ----------------
__global__ void k_gn_bg(const float* __restrict__ in, float* __restrict__ out, float eps) {
    __shared__ float rs[64];
    int b = blockIdx.x >> 5, g = blockIdx.x & 31;
    const float* base = in  + (size_t)b*16384*256 + g*8;
    float*       ob   = out + (size_t)b*16384*256 + g*8;
    float s = 0.f, s2 = 0.f;
    for (int i = threadIdx.x; i < 16384; i += 256) {
        const float4* r = (const float4*)(base + (size_t)i*256);
        float4 a = r[0], c = r[1];
        s  += a.x+a.y+a.z+a.w + c.x+c.y+c.z+c.w;
        s2 += a.x*a.x+a.y*a.y+a.z*a.z+a.w*a.w + c.x*c.x+c.y*c.y+c.z*c.z+c.w*c.w;
    }
    int lane = threadIdx.x & 31, w = threadIdx.x >> 5;
    #pragma unroll
    for (int o = 16; o; o >>= 1) {
        s  += __shfl_down_sync(0xffffffffu, s,  o);
        s2 += __shfl_down_sync(0xffffffffu, s2, o);
    }
    if (lane == 0) { rs[w] = s; rs[32 + w] = s2; }
    __syncthreads();
    if (threadIdx.x == 0) {
        float S = 0.f, S2 = 0.f;
        for (int i = 0; i < 8; i++) { S += rs[i]; S2 += rs[32 + i]; }
        rs[0] = S; rs[32] = S2;
    }
    __syncthreads();
    float mean = rs[0] * (1.f/131072.f);
    float var  = rs[32] * (1.f/131072.f) - mean*mean;
    float inv  = rsqrtf(var + eps);
    for (int i = threadIdx.x; i < 16384; i += 256) {
        const float4* r = (const float4*)(base + (size_t)i*256);
        float4 a = r[0], c = r[1];
        a.x = (a.x-mean)*inv; a.y = (a.y-mean)*inv; a.z = (a.z-mean)*inv; a.w = (a.w-mean)*inv;
        c.x = (c.x-mean)*inv; c.y = (c.y-mean)*inv; c.z = (c.z-mean)*inv; c.w = (c.w-mean)*inv;
        float4* o4 = (float4*)(ob + (size_t)i*256);
        o4[0] = a; o4[1] = c;
    }
}

// ================= tf32 tensor-core GEMM: 128x128 tile, K-tile 32 =================
// 256 thr = 8 warps (4m x 2n), warp = 32x64 = 2x8 m16n8k8 tiles.
// As[128][36] (banks 4g+tig), Bs[32][136] (banks 8tig+g): conflict-free fragments.
template<bool BIAS>
__global__ __launch_bounds__(256) void k_tgemm(
    const float* __restrict__ A, const float* __restrict__ B,
    const float* __restrict__ bias, float* __restrict__ C,
    int M, int N, int K) {
    __shared__ uint32_t As[128][36];
    __shared__ uint32_t Bs[32][136];
    int tid = threadIdx.x, lane = tid & 31, wid = tid >> 5;
    int g = lane >> 2, tig = lane & 3;
    int wm = wid >> 1, wn = wid & 1;
    int bn = blockIdx.x * 128, bm = blockIdx.y * 128;
    float acc[2][8][4] = {};
    float4 ra[4], rb[4];
    int KT = K >> 5;

    // prefetch kt=0
    #pragma unroll
    for (int i = 0; i < 4; i++) {
        int idx = tid + i*256;
        int row = idx >> 3, c4 = idx & 7;
        ra[i] = *(const float4*)(A + (size_t)(bm + row)*K + c4*4);
        int r = idx >> 5, c4b = idx & 31;
        rb[i] = *(const float4*)(B + (size_t)r*N + bn + c4b*4);
    }
    for (int kt = 0; kt < KT; kt++) {
        #pragma unroll
        for (int i = 0; i < 4; i++) {
            int idx = tid + i*256;
            int row = idx >> 3, c4 = idx & 7;
            uint4 u = make_uint4(f2tf(ra[i].x), f2tf(ra[i].y), f2tf(ra[i].z), f2tf(ra[i].w));
            *(uint4*)&As[row][c4*4] = u;
            int r = idx >> 5, c4b = idx & 31;
            uint4 v = make_uint4(f2tf(rb[i].x), f2tf(rb[i].y), f2tf(rb[i].z), f2tf(rb[i].w));
            *(uint4*)&Bs[r][c4b*4] = v;
        }
        __syncthreads();
        if (kt + 1 < KT) {
            int k0 = (kt + 1) << 5;
            #pragma unroll
            for (int i = 0; i < 4; i++) {
                int idx = tid + i*256;
                int row = idx >> 3, c4 = idx & 7;
                ra[i] = *(const float4*)(A + (size_t)(bm + row)*K + k0 + c4*4);
                int r = idx >> 5, c4b = idx & 31;
                rb[i] = *(const float4*)(B + (size_t)(k0 + r)*N + bn + c4b*4);
            }
        }
        #pragma unroll
        for (int ks = 0; ks < 4; ks++) {
            int k = ks * 8;
            uint32_t af[2][4], bf[8][2];
            #pragma unroll
            for (int mt = 0; mt < 2; mt++) {
                int r0 = wm*32 + mt*16;
                af[mt][0] = As[r0 + g][k + tig];
                af[mt][1] = As[r0 + g + 8][k + tig];
                af[mt][2] = As[r0 + g][k + tig + 4];
                af[mt][3] = As[r0 + g + 8][k + tig + 4];
            }
            #pragma unroll
            for (int nt = 0; nt < 8; nt++) {
                int c0 = wn*64 + nt*8 + g;
                bf[nt][0] = Bs[k + tig][c0];
                bf[nt][1] = Bs[k + tig + 4][c0];
            }
            #pragma unroll
            for (int mt = 0; mt < 2; mt++)
                #pragma unroll
                for (int nt = 0; nt < 8; nt++)
                    mma8(acc[mt][nt], af[mt], bf[nt]);
        }
        __syncthreads();
    }
    #pragma unroll
    for (int mt = 0; mt < 2; mt++) {
        int row = bm + wm*32 + mt*16 + g;
        #pragma unroll
        for (int nt = 0; nt < 8; nt++) {
            int col = bn + wn*64 + nt*8 + tig*2;
            float2 v0 = make_float2(acc[mt][nt][0], acc[mt][nt][1]);
            float2 v1 = make_float2(acc[mt][nt][2], acc[mt][nt][3]);
            if (BIAS) {
                float b0 = bias[col], b1v = bias[col + 1];
                v0.x += b0; v0.y += b1v; v1.x += b0; v1.y += b1v;
            }
            *(float2*)(C + (size_t)row*N + col) = v0;
            *(float2*)(C + (size_t)(row + 8)*N + col) = v1;
        }
    }
}

// ================= conv3x3 implicit GEMM on tensor cores =================
// K=2304 ordered (kyx, ci): each 32-wide K-tile lies in one (ky,kx) plane.
template<int MODE>
__global__ __launch_bounds__(256) void k_tconv(
    const float* __restrict__ In, const float* __restrict__ Wt,
    const float* __restrict__ bias, const float* __restrict__ temb,
    const float* __restrict__ gate, float* __restrict__ Out) {
    __shared__ uint32_t As[128][36];
    __shared__ uint32_t Bs[32][136];
    int tid = threadIdx.x, lane = tid & 31, wid = tid >> 5;
    int g = lane >> 2, tig = lane & 3;
    int wm = wid >> 1, wn = wid & 1;
    int bn = blockIdx.x * 128, bm = blockIdx.y * 128;
    float acc[2][8][4] = {};
    float4 ra[4], rb[4];

    // per-thread row geometry (fixed across k-tiles)
    int rrow[4], rb_r[4];
    int pb[4], pfy[4], pfx[4];
    #pragma unroll
    for (int i = 0; i < 4; i++) {
        int idx = tid + i*256;
        rrow[i] = idx >> 3;
        rb_r[i] = idx >> 5;
        int p = bm + rrow[i];
        pb[i] = p >> 14; pfy[i] = (p >> 8) & 63; pfx[i] = p & 255;
    }

    auto loadA = [&](int k0) {
        int kyx = k0 >> 8, ci0 = k0 & 255;
        int ky = kyx / 3, kx = kyx - ky*3;
        #pragma unroll
        for (int i = 0; i < 4; i++) {
            int idx = tid + i*256;
            int c4 = idx & 7;
            int fy2 = pfy[i] + ky - 1, fx2 = pfx[i] + kx - 1;
            if ((unsigned)fy2 < 64u && (unsigned)fx2 < 256u)
                ra[i] = *(const float4*)(In + (((size_t)(pb[i]*64 + fy2))*256 + fx2)*256 + ci0 + c4*4);
            else
                ra[i] = make_float4(0.f, 0.f, 0.f, 0.f);
        }
    };
    auto loadB = [&](int k0) {
        #pragma unroll
        for (int i = 0; i < 4; i++) {
            int idx = tid + i*256;
            int c4b = idx & 31;
            rb[i] = *(const float4*)(Wt + (size_t)(k0 + rb_r[i])*256 + bn + c4b*4);
        }
    };

    loadA(0); loadB(0);
    for (int kt = 0; kt < 72; kt++) {
        #pragma unroll
        for (int i = 0; i < 4; i++) {
            int idx = tid + i*256;
            int c4 = idx & 7;
            uint4 u = make_uint4(f2tf(ra[i].x), f2tf(ra[i].y), f2tf(ra[i].z), f2tf(ra[i].w));
            *(uint4*)&As[rrow[i]][c4*4] = u;
            int c4b = idx & 31;
            uint4 v = make_uint4(f2tf(rb[i].x), f2tf(rb[i].y), f2tf(rb[i].z), f2tf(rb[i].w));
            *(uint4*)&Bs[rb_r[i]][c4b*4] = v;
        }
        __syncthreads();
        if (kt + 1 < 72) { loadA((kt + 1) << 5); loadB((kt + 1) << 5); }
        #pragma unroll
        for (int ks = 0; ks < 4; ks++) {
            int k = ks * 8;
            uint32_t af[2][4], bf[8][2];
            #pragma unroll
            for (int mt = 0; mt < 2; mt++) {
                int r0 = wm*32 + mt*16;
                af[mt][0] = As[r0 + g][k + tig];
                af[mt][1] = As[r0 + g + 8][k + tig];
                af[mt][2] = As[r0 + g][k + tig + 4];
                af[mt][3] = As[r0 + g + 8][k + tig + 4];
            }
            #pragma unroll
            for (int nt = 0; nt < 8; nt++) {
                int c0 = wn*64 + nt*8 + g;
                bf[nt][0] = Bs[k + tig][c0];
                bf[nt][1] = Bs[k + tig + 4][c0];
            }
            #pragma unroll
            for (int mt = 0; mt < 2; mt++)
                #pragma unroll
                for (int nt = 0; nt < 8; nt++)
                    mma8(acc[mt][nt], af[mt], bf[nt]);
        }
        __syncthreads();
    }
    float gd = (MODE == 1) ? gate[0] : 0.f;
    #pragma unroll
    for (int mt = 0; mt < 2; mt++) {
        int row = bm + wm*32 + mt*16 + g;
        int bidx = row >> 14;   // same batch for row and row+8 (128-row tile within batch)
        #pragma unroll
        for (int nt = 0; nt < 8; nt++) {
            int col = bn + wn*64 + nt*8 + tig*2;
            float v[4] = {acc[mt][nt][0], acc[mt][nt][1], acc[mt][nt][2], acc[mt][nt][3]};
            if (MODE == 1) {
                float a0 = bias[col]     + gd * temb[bidx*256 + col];
                float a1 = bias[col + 1] + gd * temb[bidx*256 + col + 1];
                v[0] += a0; v[1] += a1; v[2] += a0; v[3] += a1;
                #pragma unroll
                for (int j = 0; j < 4; j++) v[j] = v[j] / (1.f + __expf(-v[j]));
            }
            *(float2*)(Out + (size_t)row*256 + col) = make_float2(v[0], v[1]);
            *(float2*)(Out + (size_t)(row + 8)*256 + col) = make_float2(v[2], v[3]);
        }
    }
}

// ---------------- elementwise: x += gate * h ----------------
__global__ void k_axpy_gate(float* __restrict__ x, const float* __restrict__ h,
                            const float* __restrict__ gate) {
    size_t i = ((size_t)blockIdx.x * 256 + threadIdx.x) * 4;
    float g = gate[0];
    float4 xv = *(float4*)(x + i);
    float4 hv = *(const float4*)(h + i);
    xv.x += g*hv.x; xv.y += g*hv.y; xv.z += g*hv.z; xv.w += g*hv.w;
    *(float4*)(x + i) = xv;
}

// ---------------- layer2 attention over Fq per (b,t,h) ----------------
__global__ void k_attn_freq(const float* __restrict__ qkv, float* __restrict__ y) {
    __shared__ float q[64][33], kk[64][33], v[64][33];
    __shared__ float S[64][65];
    int bt = blockIdx.x, h = blockIdx.y;
    int b = bt >> 8, t = bt & 255;
    int tid = threadIdx.x;
    for (int i = tid; i < 2048; i += 128) {
        int fq = i >> 5, d = i & 31;
        size_t base = ((size_t)((b*64 + fq)*256 + t))*768 + h*32 + d;
        q[fq][d]  = qkv[base];
        kk[fq][d] = qkv[base + 256];
        v[fq][d]  = qkv[base + 512];
    }
    __syncthreads();
    const float scale = 0.17677669529663687f;
    for (int i = tid; i < 4096; i += 128) {
        int L = i >> 6, l = i & 63;
        float s = 0.f;
        #pragma unroll
        for (int d = 0; d < 32; d++) s += q[L][d] * kk[l][d];
        S[L][l] = s * scale;
    }
    __syncthreads();
    if (tid < 64) {
        float m = -1e30f;
        for (int l = 0; l < 64; l++) m = fmaxf(m, S[tid][l]);
        float su = 0.f;
        for (int l = 0; l < 64; l++) { float e = __expf(S[tid][l] - m); S[tid][l] = e; su += e; }
        float r = 1.f / su;
        for (int l = 0; l < 64; l++) S[tid][l] *= r;
    }
    __syncthreads();
    for (int i = tid; i < 2048; i += 128) {
        int L = i >> 5, d = i & 31;
        float s = 0.f;
        #pragma unroll
        for (int l = 0; l < 64; l++) s += S[L][l] * v[l][d];
        y[((size_t)((b*64 + L)*256 + t))*256 + h*32 + d] = s;
    }
}

// ---------------- per-token rowwise GN then x += g2*y ----------------
__global__ void k_gnrow_add(const float* __restrict__ yv, float* __restrict__ x,
                            const float* __restrict__ gate) {
    int idx = blockIdx.x * 256 + threadIdx.x;
    int p = idx >> 5, g = idx & 31;
    size_t off = (size_t)p * 256 + g * 8;
    float4 a = *(const float4*)(yv + off), c = *(const float4*)(yv + off + 4);
    float vals[8] = {a.x, a.y, a.z, a.w, c.x, c.y, c.z, c.w};
    float m = 0.f;
    #pragma unroll
    for (int j = 0; j < 8; j++) m += vals[j];
    m *= 0.125f;
    float var = 0.f;
    #pragma unroll
    for (int j = 0; j < 8; j++) { float dd = vals[j] - m; var += dd * dd; }
    var *= 0.125f;
    float inv = rsqrtf(var + 1e-5f);
    float gg = gate[0];
    float4 xa = *(float4*)(x + off), xb = *(float4*)(x + off + 4);
    xa.x += gg*(vals[0]-m)*inv; xa.y += gg*(vals[1]-m)*inv;
    xa.z += gg*(vals[2]-m)*inv; xa.w += gg*(vals[3]-m)*inv;
    xb.x += gg*(vals[4]-m)*inv; xb.y += gg*(vals[5]-m)*inv;
    xb.z += gg*(vals[6]-m)*inv; xb.w += gg*(vals[7]-m)*inv;
    *(float4*)(x + off) = xa; *(float4*)(x + off + 4) = xb;
}

// ---------------- layer3 global attention (mean-query) per (bfq, h) ----------
__global__ void k_attn_time(const float* __restrict__ qkv, float* __restrict__ yout) {
    __shared__ float part[8][32];
    __shared__ float qm[32];
    __shared__ float prob[256];
    __shared__ float redm[8], reds[8];
    int bfq = blockIdx.x, h = blockIdx.y;
    int tid = threadIdx.x;
    size_t tokbase = (size_t)bfq * 256;
    int d = tid & 31, grp = tid >> 5;
    float s = 0.f;
    for (int t = grp; t < 256; t += 8)
        s += qkv[(tokbase + t)*768 + h*32 + d];
    part[grp][d] = s;
    __syncthreads();
    if (tid < 32) {
        float ss = 0.f;
        #pragma unroll
        for (int g = 0; g < 8; g++) ss += part[g][tid];
        qm[tid] = ss * (1.f/256.f);
    }
    __syncthreads();
    const float* kr = qkv + (tokbase + tid)*768 + 256 + h*32;
    float sc = 0.f;
    #pragma unroll
    for (int dd = 0; dd < 32; dd++) sc += qm[dd] * kr[dd];
    sc *= 0.17677669529663687f;
    float m = sc;
    #pragma unroll
    for (int o = 16; o; o >>= 1) m = fmaxf(m, __shfl_xor_sync(0xffffffffu, m, o));
    if ((tid & 31) == 0) redm[grp] = m;
    __syncthreads();
    float M = redm[0];
    #pragma unroll
    for (int g = 1; g < 8; g++) M = fmaxf(M, redm[g]);
    float e = __expf(sc - M);
    float su = e;
    #pragma unroll
    for (int o = 16; o; o >>= 1) su += __shfl_xor_sync(0xffffffffu, su, o);
    if ((tid & 31) == 0) reds[grp] = su;
    __syncthreads();
    float Ssum = 0.f;
    #pragma unroll
    for (int g = 0; g < 8; g++) Ssum += reds[g];
    prob[tid] = e / Ssum;
    __syncthreads();
    float acc = 0.f;
    for (int t = grp; t < 256; t += 8)
        acc += prob[t] * qkv[(tokbase + t)*768 + 512 + h*32 + d];
    part[grp][d] = acc;
    __syncthreads();
    if (tid < 32) {
        float ss = 0.f;
        #pragma unroll
        for (int g = 0; g < 8; g++) ss += part[g][tid];
        yout[(size_t)bfq*256 + h*32 + tid] = ss;
    }
}

// ---------------- layer3 epilogue ----------------
__global__ void k_gn_bcast_add(const float* __restrict__ yv, float* __restrict__ x,
                               const float* __restrict__ gate) {
    __shared__ float yn[256];
    int bfq = blockIdx.x, tid = threadIdx.x;
    if (tid < 32) {
        const float* r = yv + bfq*256 + tid*8;
        float vals[8];
        #pragma unroll
        for (int j = 0; j < 8; j++) vals[j] = r[j];
        float m = 0.f;
        #pragma unroll
        for (int j = 0; j < 8; j++) m += vals[j];
        m *= 0.125f;
        float var = 0.f;
        #pragma unroll
        for (int j = 0; j < 8; j++) { float dd = vals[j] - m; var += dd * dd; }
        var *= 0.125f;
        float inv = rsqrtf(var + 1e-5f);
        #pragma unroll
        for (int j = 0; j < 8; j++) yn[tid*8 + j] = (vals[j] - m) * inv;
    }
    __syncthreads();
    float add = gate[0] * yn[tid];
    float* xp = x + (size_t)bfq * 65536 + tid;
    for (int t = 0; t < 256; t++) xp[(size_t)t * 256] += add;
}

// ---------------- layer4 LSA ----------------
__global__ void k_attn_lsa(const float* __restrict__ qkv, float* __restrict__ y) {
    __shared__ float q[16][33], kk[16][33], v[16][33];
    __shared__ float S[16][17];
    int blk = blockIdx.x;
    size_t p0 = (size_t)(blk >> 4) * 256 + (blk & 15) * 16;
    int tid = threadIdx.x;
    int qi = tid >> 4, kj = tid & 15;
    const float scale = 0.17677669529663687f;
    for (int h = 0; h < 8; h++) {
        for (int i = tid; i < 512; i += 256) {
            int r = i >> 5, d = i & 31;
            size_t a = (p0 + r)*768 + h*32 + d;
            q[r][d] = qkv[a]; kk[r][d] = qkv[a + 256]; v[r][d] = qkv[a + 512];
        }
        __syncthreads();
        float s = 0.f;
        #pragma unroll
        for (int d = 0; d < 32; d++) s += q[qi][d] * kk[kj][d];
        S[qi][kj] = s * scale;
        __syncthreads();
        if (tid < 16) {
            float m = -1e30f;
            for (int j = 0; j < 16; j++) m = fmaxf(m, S[tid][j]);
            float su = 0.f;
            for (int j = 0; j < 16; j++) { float e = __expf(S[tid][j] - m); S[tid][j] = e; su += e; }
            float r = 1.f / su;
            for (int j = 0; j < 16; j++) S[tid][j] *= r;
        }
        __syncthreads();
        for (int i = tid; i < 512; i += 256) {
            int r = i >> 5, d = i & 31;
            float s2 = 0.f;
            #pragma unroll
            for (int j = 0; j < 16; j++) s2 += S[r][j] * v[j][d];
            y[(p0 + r)*256 + h*32 + d] = s2;
        }
        __syncthreads();
    }
}

// =====================================================================================
extern "C" void kernel_launch(void* const* d_in, const int* in_sizes, int n_in,
                              void* d_out, int out_size) {
    const float* x     = (const float*)d_in[0];
    const float* temb  = (const float*)d_in[1];
    const float* w1    = (const float*)d_in[2];
    const float* b1    = (const float*)d_in[3];
    const float* w2    = (const float*)d_in[4];
    const float* gdiff = (const float*)d_in[5];
    const float* gres  = (const float*)d_in[6];
    const float* g2    = (const float*)d_in[7];
    const float* g3    = (const float*)d_in[8];
    const float* qkv2w = (const float*)d_in[9];
    const float* qkv2b = (const float*)d_in[10];
    const float* out2w = (const float*)d_in[11];
    const float* qkv3w = (const float*)d_in[12];
    const float* qkv3b = (const float*)d_in[13];
    const float* out3w = (const float*)d_in[14];
    const float* lsaqw = (const float*)d_in[15];
    const float* lsaow = (const float*)d_in[16];
    float* out = (float*)d_out;

    float *px, *ph, *ph2, *py, *pqkv, *pa3, *pa3b, *pwt;
    cudaGetSymbolAddress((void**)&px,   g_x);
    cudaGetSymbolAddress((void**)&ph,   g_h);
    cudaGetSymbolAddress((void**)&ph2,  g_h2);
    cudaGetSymbolAddress((void**)&py,   g_y);
    cudaGetSymbolAddress((void**)&pqkv, g_qkv);
    cudaGetSymbolAddress((void**)&pa3,  g_a3);
    cudaGetSymbolAddress((void**)&pa3b, g_a3b);
    cudaGetSymbolAddress((void**)&pwt,  g_wt);

    dim3 tb32(32, 8);

    k_nchw_to_nhwc<<<dim3(8, 8, 256), tb32>>>(x, px);

    // ---- Residual block ----
    k_gn_bg<<<128, 256>>>(px, ph, 1e-6f);
    k_wtrans<<<2304, 256>>>(w1, pwt);
    k_tconv<1><<<dim3(2, 512), 256>>>(ph, pwt, b1, temb, gdiff, ph2);
    k_gn_bg<<<128, 256>>>(ph2, ph, 1e-6f);
    k_wtrans<<<2304, 256>>>(w2, pwt);
    k_tconv<0><<<dim3(2, 512), 256>>>(ph, pwt, nullptr, nullptr, nullptr, ph2);
    k_gn_bg<<<128, 256>>>(ph2, ph, 1e-6f);
    k_axpy_gate<<<16384, 256>>>(px, ph, gres);

    // ---- layer2 ----
    k_tgemm<true><<<dim3(6, 512), 256>>>(px, qkv2w, qkv2b, pqkv, NTOK, 768, 256);
    k_attn_freq<<<dim3(1024, 8), 128>>>(pqkv, py);
    k_tgemm<false><<<dim3(2, 512), 256>>>(py, out2w, nullptr, ph, NTOK, 256, 256);
    k_gnrow_add<<<8192, 256>>>(ph, px, g2);

    // ---- layer3 ----
    k_tgemm<true><<<dim3(6, 512), 256>>>(px, qkv3w, qkv3b, pqkv, NTOK, 768, 256);
    k_attn_time<<<dim3(256, 8), 256>>>(pqkv, pa3);
    k_tgemm<false><<<dim3(2, 2), 256>>>(pa3, out3w, nullptr, pa3b, 256, 256, 256);
    k_gn_bcast_add<<<256, 256>>>(pa3b, px, g3);

    // ---- layer4 ----
    k_gn_bg<<<128, 256>>>(px, ph, 1e-5f);
    k_tgemm<false><<<dim3(6, 512), 256>>>(ph, lsaqw, nullptr, pqkv, NTOK, 768, 256);
    k_attn_lsa<<<4096, 256>>>(pqkv, py);
    k_tgemm<false><<<dim3(2, 512), 256>>>(py, lsaow, nullptr, ph, NTOK, 256, 256);

    k_nhwc_to_nchw_add<<<dim3(8, 8, 256), tb32>>>(px, ph, out);
}

// round 6
// speedup vs baseline: 2.9828x; 1.2318x over previous
#include <cuda_runtime.h>
#include <cstdint>
#include <math.h>

// B=4, C=256, Fq=64, T=256, HEADS=8, Dh=32, GROUPS=32, WIN=16
#define NTOK   65536
#define ELEMS  16777216

// ---------------- scratch ----------------
__device__ float g_x[ELEMS];
__device__ float g_h[ELEMS];
__device__ float g_h2[ELEMS];       // also: tf32 shadow of g_x for qkv GEMM A
__device__ float g_y[ELEMS];
__device__ float g_qkv[3*ELEMS];
__device__ float g_a3[65536];
__device__ float g_a3b[65536];
__device__ float g_wt[589824];      // conv weights, tf32, [k=(kyx*256+ci)][co]
__device__ float g_wq2[196608];
__device__ float g_wo2[65536];
__device__ float g_wq3[196608];
__device__ float g_wo3[65536];
__device__ float g_wq4[196608];
__device__ float g_wo4[65536];

// ---------------- tf32 helpers ----------------
__device__ __forceinline__ uint32_t f2tf(float x) {
    uint32_t r; asm("cvt.rna.tf32.f32 %0, %1;" : "=r"(r) : "f"(x)); return r;
}
__device__ __forceinline__ float tf32r(float x) { return __uint_as_float(f2tf(x)); }
__device__ __forceinline__ void mma8(float* d, const uint32_t* a, const uint32_t* b) {
    asm volatile("mma.sync.aligned.m16n8k8.row.col.f32.tf32.tf32.f32 "
        "{%0,%1,%2,%3}, {%4,%5,%6,%7}, {%8,%9}, {%0,%1,%2,%3};"
        : "+f"(d[0]), "+f"(d[1]), "+f"(d[2]), "+f"(d[3])
        : "r"(a[0]), "r"(a[1]), "r"(a[2]), "r"(a[3]), "r"(b[0]), "r"(b[1]));
}
__device__ __forceinline__ void cpa16(uint32_t dst, const void* src, int sz) {
    asm volatile("cp.async.cg.shared.global [%0], [%1], 16, %2;" :: "r"(dst), "l"(src), "r"(sz));
}
__device__ __forceinline__ void cpa_commit() { asm volatile("cp.async.commit_group;"); }
__device__ __forceinline__ void cpa_wait0()  { asm volatile("cp.async.wait_group 0;"); }

// smem stage layout (words): A[128][36] at 0, B[32][136] at 4608; stage = 8960 words
#define STAGE_W 8960
#define BS_OFF  4608

// ---------------- transposes ----------------
__global__ void k_nchw_to_nhwc(const float* __restrict__ in, float* __restrict__ out) {
    __shared__ float tile[32][33];
    int bfq = blockIdx.z, b = bfq >> 6, fq = bfq & 63;
    int t0 = blockIdx.x * 32, c0 = blockIdx.y * 32;
    for (int r = threadIdx.y; r < 32; r += 8)
        tile[r][threadIdx.x] = in[(((size_t)b*256 + c0 + r)*64 + fq)*256 + t0 + threadIdx.x];
    __syncthreads();
    for (int r = threadIdx.y; r < 32; r += 8)
        out[((size_t)bfq*256 + t0 + r)*256 + c0 + threadIdx.x] = tile[threadIdx.x][r];
}

__global__ void k_nhwc_to_nchw_add(const float* __restrict__ xa, const float* __restrict__ xb,
                                   float* __restrict__ out) {
    __shared__ float tile[32][33];
    int bfq = blockIdx.z, b = bfq >> 6, fq = bfq & 63;
    int t0 = blockIdx.x * 32, c0 = blockIdx.y * 32;
    for (int r = threadIdx.y; r < 32; r += 8) {
        size_t p = ((size_t)bfq*256 + t0 + r)*256 + c0 + threadIdx.x;
        tile[r][threadIdx.x] = xa[p] + xb[p];
    }
    __syncthreads();
    for (int r = threadIdx.y; r < 32; r += 8)
        out[(((size_t)b*256 + c0 + r)*64 + fq)*256 + t0 + threadIdx.x] = tile[threadIdx.x][r];
}

// elementwise tf32 weight convert
__global__ void k_cvt(const float* __restrict__ in, float* __restrict__ out, int n) {
    int i = blockIdx.x * 256 + threadIdx.x;
    if (i < n) out[i] = tf32r(in[i]);
}

// conv weight transpose + tf32: wt[(kyx*256+ci)*256+co] = tf32(w[co*2304 + ci*9 + kyx])
__global__ void k_wtrans(const float* __restrict__ w, float* __restrict__ wt) {
    int idx = blockIdx.x * 256 + threadIdx.x;
    int co = idx & 255, k = idx >> 8;
    int kyx = k >> 8, ci = k & 255;
    wt[idx] = tf32r(w[(size_t)co * 2304 + ci * 9 + kyx]);
}

// ---------------- GroupNorm per (b, g); ROUND -> output tf32-rounded ----------------
template<bool ROUND>
__global__ void k_gn_bg(const float* __restrict__ in, float* __restrict__ out, float eps) {
    __shared__ float rs[64];
    int b = blockIdx.x >> 5, g = blockIdx.x & 31;
    const float* base = in  + (size_t)b*16384*256 + g*8;
    float*       ob   = out + (size_t)b*16384*256 + g*8;
    float s = 0.f, s2 = 0.f;
    for (int i = threadIdx.x; i < 16384; i += 256) {
        const float4* r = (const float4*)(base + (size_t)i*256);
        float4 a = r[0], c = r[1];
        s  += a.x+a.y+a.z+a.w + c.x+c.y+c.z+c.w;
        s2 += a.x*a.x+a.y*a.y+a.z*a.z+a.w*a.w + c.x*c.x+c.y*c.y+c.z*c.z+c.w*c.w;
    }
    int lane = threadIdx.x & 31, w = threadIdx.x >> 5;
    #pragma unroll
    for (int o = 16; o; o >>= 1) {
        s  += __shfl_down_sync(0xffffffffu, s,  o);
        s2 += __shfl_down_sync(0xffffffffu, s2, o);
    }
    if (lane == 0) { rs[w] = s; rs[32 + w] = s2; }
    __syncthreads();
    if (threadIdx.x == 0) {
        float S = 0.f, S2 = 0.f;
        for (int i = 0; i < 8; i++) { S += rs[i]; S2 += rs[32 + i]; }
        rs[0] = S; rs[32] = S2;
    }
    __syncthreads();
    float mean = rs[0] * (1.f/131072.f);
    float var  = rs[32] * (1.f/131072.f) - mean*mean;
    float inv  = rsqrtf(var + eps);
    for (int i = threadIdx.x; i < 16384; i += 256) {
        const float4* r = (const float4*)(base + (size_t)i*256);
        float4 a = r[0], c = r[1];
        a.x = (a.x-mean)*inv; a.y = (a.y-mean)*inv; a.z = (a.z-mean)*inv; a.w = (a.w-mean)*inv;
        c.x = (c.x-mean)*inv; c.y = (c.y-mean)*inv; c.z = (c.z-mean)*inv; c.w = (c.w-mean)*inv;
        if (ROUND) {
            a.x = tf32r(a.x); a.y = tf32r(a.y); a.z = tf32r(a.z); a.w = tf32r(a.w);
            c.x = tf32r(c.x); c.y = tf32r(c.y); c.z = tf32r(c.z); c.w = tf32r(c.w);
        }
        float4* o4 = (float4*)(ob + (size_t)i*256);
        o4[0] = a; o4[1] = c;
    }
}

// ============ pipelined tf32 GEMM: cp.async double-buffer, 128x128 tile, Kt=32 ============
// Operands MUST already be tf32-rounded values.
template<bool BIAS>
__global__ __launch_bounds__(256, 2) void k_pgemm(
    const float* __restrict__ A, const float* __restrict__ B,
    const float* __restrict__ bias, float* __restrict__ C,
    int M, int N, int K) {
    extern __shared__ uint32_t dynsm[];
    uint32_t sbase = (uint32_t)__cvta_generic_to_shared(dynsm);
    int tid = threadIdx.x, lane = tid & 31, wid = tid >> 5;
    int g = lane >> 2, tig = lane & 3;
    int wm = wid >> 1, wn = wid & 1;
    int bn = blockIdx.x * 128, bm = blockIdx.y * 128;
    float acc[2][8][4] = {};
    int KT = K >> 5;

    auto copy = [&](int kt, int s) {
        int k0 = kt << 5;
        #pragma unroll
        for (int i = 0; i < 4; i++) {
            int idx = tid + i*256;
            int row = idx >> 3, c4 = idx & 7;
            cpa16(sbase + (s*STAGE_W + row*36 + c4*4)*4,
                  A + (size_t)(bm + row)*K + k0 + c4*4, 16);
            int r = idx >> 5, cb = idx & 31;
            cpa16(sbase + (s*STAGE_W + BS_OFF + r*136 + cb*4)*4,
                  B + (size_t)(k0 + r)*N + bn + cb*4, 16);
        }
        cpa_commit();
    };

    copy(0, 0);
    for (int kt = 0; kt < KT; kt++) {
        cpa_wait0();
        __syncthreads();
        if (kt + 1 < KT) copy(kt + 1, (kt + 1) & 1);
        const uint32_t* As = dynsm + (kt & 1)*STAGE_W;
        const uint32_t* Bs = As + BS_OFF;
        #pragma unroll
        for (int ks = 0; ks < 4; ks++) {
            int k = ks * 8;
            uint32_t af[2][4], bf[8][2];
            #pragma unroll
            for (int mt = 0; mt < 2; mt++) {
                int r0 = wm*32 + mt*16;
                af[mt][0] = As[(r0 + g)*36 + k + tig];
                af[mt][1] = As[(r0 + g + 8)*36 + k + tig];
                af[mt][2] = As[(r0 + g)*36 + k + tig + 4];
                af[mt][3] = As[(r0 + g + 8)*36 + k + tig + 4];
            }
            #pragma unroll
            for (int nt = 0; nt < 8; nt++) {
                int c0 = wn*64 + nt*8 + g;
                bf[nt][0] = Bs[(k + tig)*136 + c0];
                bf[nt][1] = Bs[(k + tig + 4)*136 + c0];
            }
            #pragma unroll
            for (int mt = 0; mt < 2; mt++)
                #pragma unroll
                for (int nt = 0; nt < 8; nt++)
                    mma8(acc[mt][nt], af[mt], bf[nt]);
        }
    }
    #pragma unroll
    for (int mt = 0; mt < 2; mt++) {
        int row = bm + wm*32 + mt*16 + g;
        #pragma unroll
        for (int nt = 0; nt < 8; nt++) {
            int col = bn + wn*64 + nt*8 + tig*2;
            float2 v0 = make_float2(acc[mt][nt][0], acc[mt][nt][1]);
            float2 v1 = make_float2(acc[mt][nt][2], acc[mt][nt][3]);
            if (BIAS) {
                float b0 = bias[col], b1v = bias[col + 1];
                v0.x += b0; v0.y += b1v; v1.x += b0; v1.y += b1v;
            }
            *(float2*)(C + (size_t)row*N + col) = v0;
            *(float2*)(C + (size_t)(row + 8)*N + col) = v1;
        }
    }
}

// ============ pipelined conv3x3 implicit GEMM (cp.async, zfill boundary) ============
template<int MODE>
__global__ __launch_bounds__(256, 2) void k_pconv(
    const float* __restrict__ In, const float* __restrict__ Wt,
    const float* __restrict__ bias, const float* __restrict__ temb,
    const float* __restrict__ gate, float* __restrict__ Out) {
    extern __shared__ uint32_t dynsm[];
    uint32_t sbase = (uint32_t)__cvta_generic_to_shared(dynsm);
    int tid = threadIdx.x, lane = tid & 31, wid = tid >> 5;
    int g = lane >> 2, tig = lane & 3;
    int wm = wid >> 1, wn = wid & 1;
    int bn = blockIdx.x * 128, bm = blockIdx.y * 128;
    float acc[2][8][4] = {};

    int pb[4], pfy[4], pfx[4];
    #pragma unroll
    for (int i = 0; i < 4; i++) {
        int p = bm + ((tid + i*256) >> 3);
        pb[i] = p >> 14; pfy[i] = (p >> 8) & 63; pfx[i] = p & 255;
    }

    auto copy = [&](int kt, int s) {
        int k0 = kt << 5;
        int kyx = k0 >> 8, ci0 = k0 & 255;
        int ky = kyx / 3, kx = kyx - ky*3;
        #pragma unroll
        for (int i = 0; i < 4; i++) {
            int idx = tid + i*256;
            int row = idx >> 3, c4 = idx & 7;
            int fy2 = pfy[i] + ky - 1, fx2 = pfx[i] + kx - 1;
            bool v = ((unsigned)fy2 < 64u) && ((unsigned)fx2 < 256u);
            int fy2c = v ? fy2 : 0, fx2c = v ? fx2 : 0;
            cpa16(sbase + (s*STAGE_W + row*36 + c4*4)*4,
                  In + (((size_t)(pb[i]*64 + fy2c))*256 + fx2c)*256 + ci0 + c4*4,
                  v ? 16 : 0);
            int r = idx >> 5, cb = idx & 31;
            cpa16(sbase + (s*STAGE_W + BS_OFF + r*136 + cb*4)*4,
                  Wt + (size_t)(k0 + r)*256 + bn + cb*4, 16);
        }
        cpa_commit();
    };

    copy(0, 0);
    for (int kt = 0; kt < 72; kt++) {
        cpa_wait0();
        __syncthreads();
        if (kt + 1 < 72) copy(kt + 1, (kt + 1) & 1);
        const uint32_t* As = dynsm + (kt & 1)*STAGE_W;
        const uint32_t* Bs = As + BS_OFF;
        #pragma unroll
        for (int ks = 0; ks < 4; ks++) {
            int k = ks * 8;
            uint32_t af[2][4], bf[8][2];
            #pragma unroll
            for (int mt = 0; mt < 2; mt++) {
                int r0 = wm*32 + mt*16;
                af[mt][0] = As[(r0 + g)*36 + k + tig];
                af[mt][1] = As[(r0 + g + 8)*36 + k + tig];
                af[mt][2] = As[(r0 + g)*36 + k + tig + 4];
                af[mt][3] = As[(r0 + g + 8)*36 + k + tig + 4];
            }
            #pragma unroll
            for (int nt = 0; nt < 8; nt++) {
                int c0 = wn*64 + nt*8 + g;
                bf[nt][0] = Bs[(k + tig)*136 + c0];
                bf[nt][1] = Bs[(k + tig + 4)*136 + c0];
            }
            #pragma unroll
            for (int mt = 0; mt < 2; mt++)
                #pragma unroll
                for (int nt = 0; nt < 8; nt++)
                    mma8(acc[mt][nt], af[mt], bf[nt]);
        }
    }
    float gd = (MODE == 1) ? gate[0] : 0.f;
    #pragma unroll
    for (int mt = 0; mt < 2; mt++) {
        int row = bm + wm*32 + mt*16 + g;
        int bidx = row >> 14;
        #pragma unroll
        for (int nt = 0; nt < 8; nt++) {
            int col = bn + wn*64 + nt*8 + tig*2;
            float v[4] = {acc[mt][nt][0], acc[mt][nt][1], acc[mt][nt][2], acc[mt][nt][3]};
            if (MODE == 1) {
                float a0 = bias[col]     + gd * temb[bidx*256 + col];
                float a1 = bias[col + 1] + gd * temb[bidx*256 + col + 1];
                v[0] += a0; v[1] += a1; v[2] += a0; v[3] += a1;
                #pragma unroll
                for (int j = 0; j < 4; j++) v[j] = v[j] / (1.f + __expf(-v[j]));
            }
            *(float2*)(Out + (size_t)row*256 + col) = make_float2(v[0], v[1]);
            *(float2*)(Out + (size_t)(row + 8)*256 + col) = make_float2(v[2], v[3]);
        }
    }
}

// ---------------- x += gate*h; also write tf32 shadow of new x ----------------
__global__ void k_axpy_gate(float* __restrict__ x, const float* __restrict__ h,
                            const float* __restrict__ gate, float* __restrict__ xs) {
    size_t i = ((size_t)blockIdx.x * 256 + threadIdx.x) * 4;
    float g = gate[0];
    float4 xv = *(float4*)(x + i);
    float4 hv = *(const float4*)(h + i);
    xv.x += g*hv.x; xv.y += g*hv.y; xv.z += g*hv.z; xv.w += g*hv.w;
    *(float4*)(x + i) = xv;
    float4 sv = make_float4(tf32r(xv.x), tf32r(xv.y), tf32r(xv.z), tf32r(xv.w));
    *(float4*)(xs + i) = sv;
}

// ---------------- layer2 attention over Fq per (b,t,h); output tf32-rounded ----------
__global__ void k_attn_freq(const float* __restrict__ qkv, float* __restrict__ y) {
    __shared__ float q[64][33], kk[64][33], v[64][33];
    __shared__ float S[64][65];
    int bt = blockIdx.x, h = blockIdx.y;
    int b = bt >> 8, t = bt & 255;
    int tid = threadIdx.x;
    for (int i = tid; i < 2048; i += 128) {
        int fq = i >> 5, d = i & 31;
        size_t base = ((size_t)((b*64 + fq)*256 + t))*768 + h*32 + d;
        q[fq][d]  = qkv[base];
        kk[fq][d] = qkv[base + 256];
        v[fq][d]  = qkv[base + 512];
    }
    __syncthreads();
    const float scale = 0.17677669529663687f;
    for (int i = tid; i < 4096; i += 128) {
        int L = i >> 6, l = i & 63;
        float s = 0.f;
        #pragma unroll
        for (int d = 0; d < 32; d++) s += q[L][d] * kk[l][d];
        S[L][l] = s * scale;
    }
    __syncthreads();
    if (tid < 64) {
        float m = -1e30f;
        for (int l = 0; l < 64; l++) m = fmaxf(m, S[tid][l]);
        float su = 0.f;
        for (int l = 0; l < 64; l++) { float e = __expf(S[tid][l] - m); S[tid][l] = e; su += e; }
        float r = 1.f / su;
        for (int l = 0; l < 64; l++) S[tid][l] *= r;
    }
    __syncthreads();
    for (int i = tid; i < 2048; i += 128) {
        int L = i >> 5, d = i & 31;
        float s = 0.f;
        #pragma unroll
        for (int l = 0; l < 64; l++) s += S[L][l] * v[l][d];
        y[((size_t)((b*64 + L)*256 + t))*256 + h*32 + d] = tf32r(s);
    }
}

// ---------------- per-token GN then x += g2*y; write tf32 shadow of new x ----------
__global__ void k_gnrow_add(const float* __restrict__ yv, float* __restrict__ x,
                            const float* __restrict__ gate, float* __restrict__ xs) {
    int idx = blockIdx.x * 256 + threadIdx.x;
    int p = idx >> 5, g = idx & 31;
    size_t off = (size_t)p * 256 + g * 8;
    float4 a = *(const float4*)(yv + off), c = *(const float4*)(yv + off + 4);
    float vals[8] = {a.x, a.y, a.z, a.w, c.x, c.y, c.z, c.w};
    float m = 0.f;
    #pragma unroll
    for (int j = 0; j < 8; j++) m += vals[j];
    m *= 0.125f;
    float var = 0.f;
    #pragma unroll
    for (int j = 0; j < 8; j++) { float dd = vals[j] - m; var += dd * dd; }
    var *= 0.125f;
    float inv = rsqrtf(var + 1e-5f);
    float gg = gate[0];
    float xo[8];
    float4 xa = *(float4*)(x + off), xb = *(float4*)(x + off + 4);
    xo[0]=xa.x; xo[1]=xa.y; xo[2]=xa.z; xo[3]=xa.w;
    xo[4]=xb.x; xo[5]=xb.y; xo[6]=xb.z; xo[7]=xb.w;
    #pragma unroll
    for (int j = 0; j < 8; j++) xo[j] += gg * (vals[j] - m) * inv;
    *(float4*)(x + off)     = make_float4(xo[0], xo[1], xo[2], xo[3]);
    *(float4*)(x + off + 4) = make_float4(xo[4], xo[5], xo[6], xo[7]);
    *(float4*)(xs + off)     = make_float4(tf32r(xo[0]), tf32r(xo[1]), tf32r(xo[2]), tf32r(xo[3]));
    *(float4*)(xs + off + 4) = make_float4(tf32r(xo[4]), tf32r(xo[5]), tf32r(xo[6]), tf32r(xo[7]));
}

// ---------------- layer3 global attention per (bfq, h); output tf32-rounded --------
__global__ void k_attn_time(const float* __restrict__ qkv, float* __restrict__ yout) {
    __shared__ float part[8][32];
    __shared__ float qm[32];
    __shared__ float prob[256];
    __shared__ float redm[8], reds[8];
    int bfq = blockIdx.x, h = blockIdx.y;
    int tid = threadIdx.x;
    size_t tokbase = (size_t)bfq * 256;
    int d = tid & 31, grp = tid >> 5;
    float s = 0.f;
    for (int t = grp; t < 256; t += 8)
        s += qkv[(tokbase + t)*768 + h*32 + d];
    part[grp][d] = s;
    __syncthreads();
    if (tid < 32) {
        float ss = 0.f;
        #pragma unroll
        for (int g = 0; g < 8; g++) ss += part[g][tid];
        qm[tid] = ss * (1.f/256.f);
    }
    __syncthreads();
    const float* kr = qkv + (tokbase + tid)*768 + 256 + h*32;
    float sc = 0.f;
    #pragma unroll
    for (int dd = 0; dd < 32; dd++) sc += qm[dd] * kr[dd];
    sc *= 0.17677669529663687f;
    float m = sc;
    #pragma unroll
    for (int o = 16; o; o >>= 1) m = fmaxf(m, __shfl_xor_sync(0xffffffffu, m, o));
    if ((tid & 31) == 0) redm[grp] = m;
    __syncthreads();
    float M = redm[0];
    #pragma unroll
    for (int g = 1; g < 8; g++) M = fmaxf(M, redm[g]);
    float e = __expf(sc - M);
    float su = e;
    #pragma unroll
    for (int o = 16; o; o >>= 1) su += __shfl_xor_sync(0xffffffffu, su, o);
    if ((tid & 31) == 0) reds[grp] = su;
    __syncthreads();
    float Ssum = 0.f;
    #pragma unroll
    for (int g = 0; g < 8; g++) Ssum += reds[g];
    prob[tid] = e / Ssum;
    __syncthreads();
    float acc = 0.f;
    for (int t = grp; t < 256; t += 8)
        acc += prob[t] * qkv[(tokbase + t)*768 + 512 + h*32 + d];
    part[grp][d] = acc;
    __syncthreads();
    if (tid < 32) {
        float ss = 0.f;
        #pragma unroll
        for (int g = 0; g < 8; g++) ss += part[g][tid];
        yout[(size_t)bfq*256 + h*32 + tid] = tf32r(ss);
    }
}

// ---------------- layer3 epilogue ----------------
__global__ void k_gn_bcast_add(const float* __restrict__ yv, float* __restrict__ x,
                               const float* __restrict__ gate) {
    __shared__ float yn[256];
    int bfq = blockIdx.x, tid = threadIdx.x;
    if (tid < 32) {
        const float* r = yv + bfq*256 + tid*8;
        float vals[8];
        #pragma unroll
        for (int j = 0; j < 8; j++) vals[j] = r[j];
        float m = 0.f;
        #pragma unroll
        for (int j = 0; j < 8; j++) m += vals[j];
        m *= 0.125f;
        float var = 0.f;
        #pragma unroll
        for (int j = 0; j < 8; j++) { float dd = vals[j] - m; var += dd * dd; }
        var *= 0.125f;
        float inv = rsqrtf(var + 1e-5f);
        #pragma unroll
        for (int j = 0; j < 8; j++) yn[tid*8 + j] = (vals[j] - m) * inv;
    }
    __syncthreads();
    float add = gate[0] * yn[tid];
    float* xp = x + (size_t)bfq * 65536 + tid;
    for (int t = 0; t < 256; t++) xp[(size_t)t * 256] += add;
}

// ---------------- layer4 LSA; output tf32-rounded ----------------
__global__ void k_attn_lsa(const float* __restrict__ qkv, float* __restrict__ y) {
    __shared__ float q[16][33], kk[16][33], v[16][33];
    __shared__ float S[16][17];
    int blk = blockIdx.x;
    size_t p0 = (size_t)(blk >> 4) * 256 + (blk & 15) * 16;
    int tid = threadIdx.x;
    int qi = tid >> 4, kj = tid & 15;
    const float scale = 0.17677669529663687f;
    for (int h = 0; h < 8; h++) {
        for (int i = tid; i < 512; i += 256) {
            int r = i >> 5, d = i & 31;
            size_t a = (p0 + r)*768 + h*32 + d;
            q[r][d] = qkv[a]; kk[r][d] = qkv[a + 256]; v[r][d] = qkv[a + 512];
        }
        __syncthreads();
        float s = 0.f;
        #pragma unroll
        for (int d = 0; d < 32; d++) s += q[qi][d] * kk[kj][d];
        S[qi][kj] = s * scale;
        __syncthreads();
        if (tid < 16) {
            float m = -1e30f;
            for (int j = 0; j < 16; j++) m = fmaxf(m, S[tid][j]);
            float su = 0.f;
            for (int j = 0; j < 16; j++) { float e = __expf(S[tid][j] - m); S[tid][j] = e; su += e; }
            float r = 1.f / su;
            for (int j = 0; j < 16; j++) S[tid][j] *= r;
        }
        __syncthreads();
        for (int i = tid; i < 512; i += 256) {
            int r = i >> 5, d = i & 31;
            float s2 = 0.f;
            #pragma unroll
            for (int j = 0; j < 16; j++) s2 += S[r][j] * v[j][d];
            y[(p0 + r)*256 + h*32 + d] = tf32r(s2);
        }
        __syncthreads();
    }
}

// =====================================================================================
extern "C" void kernel_launch(void* const* d_in, const int* in_sizes, int n_in,
                              void* d_out, int out_size) {
    const float* x     = (const float*)d_in[0];
    const float* temb  = (const float*)d_in[1];
    const float* w1    = (const float*)d_in[2];
    const float* b1    = (const float*)d_in[3];
    const float* w2    = (const float*)d_in[4];
    const float* gdiff = (const float*)d_in[5];
    const float* gres  = (const float*)d_in[6];
    const float* g2    = (const float*)d_in[7];
    const float* g3    = (const float*)d_in[8];
    const float* qkv2w = (const float*)d_in[9];
    const float* qkv2b = (const float*)d_in[10];
    const float* out2w = (const float*)d_in[11];
    const float* qkv3w = (const float*)d_in[12];
    const float* qkv3b = (const float*)d_in[13];
    const float* out3w = (const float*)d_in[14];
    const float* lsaqw = (const float*)d_in[15];
    const float* lsaow = (const float*)d_in[16];
    float* out = (float*)d_out;

    float *px, *ph, *ph2, *py, *pqkv, *pa3, *pa3b, *pwt;
    float *pwq2, *pwo2, *pwq3, *pwo3, *pwq4, *pwo4;
    cudaGetSymbolAddress((void**)&px,   g_x);
    cudaGetSymbolAddress((void**)&ph,   g_h);
    cudaGetSymbolAddress((void**)&ph2,  g_h2);
    cudaGetSymbolAddress((void**)&py,   g_y);
    cudaGetSymbolAddress((void**)&pqkv, g_qkv);
    cudaGetSymbolAddress((void**)&pa3,  g_a3);
    cudaGetSymbolAddress((void**)&pa3b, g_a3b);
    cudaGetSymbolAddress((void**)&pwt,  g_wt);
    cudaGetSymbolAddress((void**)&pwq2, g_wq2);
    cudaGetSymbolAddress((void**)&pwo2, g_wo2);
    cudaGetSymbolAddress((void**)&pwq3, g_wq3);
    cudaGetSymbolAddress((void**)&pwo3, g_wo3);
    cudaGetSymbolAddress((void**)&pwq4, g_wq4);
    cudaGetSymbolAddress((void**)&pwo4, g_wo4);

    const int SMEM = 2 * STAGE_W * 4;   // 71680 B
    cudaFuncSetAttribute(k_pgemm<true>,  cudaFuncAttributeMaxDynamicSharedMemorySize, SMEM);
    cudaFuncSetAttribute(k_pgemm<false>, cudaFuncAttributeMaxDynamicSharedMemorySize, SMEM);
    cudaFuncSetAttribute(k_pconv<0>,     cudaFuncAttributeMaxDynamicSharedMemorySize, SMEM);
    cudaFuncSetAttribute(k_pconv<1>,     cudaFuncAttributeMaxDynamicSharedMemorySize, SMEM);

    dim3 tb32(32, 8);

    k_nchw_to_nhwc<<<dim3(8, 8, 256), tb32>>>(x, px);

    // weight tf32 conversions (independent of activation flow)
    k_cvt<<<768, 256>>>(qkv2w, pwq2, 196608);
    k_cvt<<<256, 256>>>(out2w, pwo2, 65536);
    k_cvt<<<768, 256>>>(qkv3w, pwq3, 196608);
    k_cvt<<<256, 256>>>(out3w, pwo3, 65536);
    k_cvt<<<768, 256>>>(lsaqw, pwq4, 196608);
    k_cvt<<<256, 256>>>(lsaow, pwo4, 65536);

    // ---- Residual block ----
    k_gn_bg<true><<<128, 256>>>(px, ph, 1e-6f);
    k_wtrans<<<2304, 256>>>(w1, pwt);
    k_pconv<1><<<dim3(2, 512), 256, SMEM>>>(ph, pwt, b1, temb, gdiff, ph2);
    k_gn_bg<true><<<128, 256>>>(ph2, ph, 1e-6f);
    k_wtrans<<<2304, 256>>>(w2, pwt);
    k_pconv<0><<<dim3(2, 512), 256, SMEM>>>(ph, pwt, nullptr, nullptr, nullptr, ph2);
    k_gn_bg<false><<<128, 256>>>(ph2, ph, 1e-6f);
    k_axpy_gate<<<16384, 256>>>(px, ph, gres, ph2);   // ph2 = tf32 shadow of px

    // ---- layer2 ----
    k_pgemm<true><<<dim3(6, 512), 256, SMEM>>>(ph2, pwq2, qkv2b, pqkv, NTOK, 768, 256);
    k_attn_freq<<<dim3(1024, 8), 128>>>(pqkv, py);
    k_pgemm<false><<<dim3(2, 512), 256, SMEM>>>(py, pwo2, nullptr, ph, NTOK, 256, 256);
    k_gnrow_add<<<8192, 256>>>(ph, px, g2, ph2);      // update px + refresh shadow

    // ---- layer3 ----
    k_pgemm<true><<<dim3(6, 512), 256, SMEM>>>(ph2, pwq3, qkv3b, pqkv, NTOK, 768, 256);
    k_attn_time<<<dim3(256, 8), 256>>>(pqkv, pa3);
    k_pgemm<false><<<dim3(2, 2), 256, SMEM>>>(pa3, pwo3, nullptr, pa3b, 256, 256, 256);
    k_gn_bcast_add<<<256, 256>>>(pa3b, px, g3);

    // ---- layer4 ----
    k_gn_bg<true><<<128, 256>>>(px, ph, 1e-5f);
    k_pgemm<false><<<dim3(6, 512), 256, SMEM>>>(ph, pwq4, nullptr, pqkv, NTOK, 768, 256);
    k_attn_lsa<<<4096, 256>>>(pqkv, py);
    k_pgemm<false><<<dim3(2, 512), 256, SMEM>>>(py, pwo4, nullptr, ph, NTOK, 256, 256);

    k_nhwc_to_nchw_add<<<dim3(8, 8, 256), tb32>>>(px, ph, out);
}

// round 7
// speedup vs baseline: 3.0954x; 1.0377x over previous
#include <cuda_runtime.h>
#include <cstdint>
#include <math.h>

// B=4, C=256, Fq=64, T=256, HEADS=8, Dh=32, GROUPS=32, WIN=16
#define NTOK   65536
#define ELEMS  16777216

// ---------------- scratch ----------------
__device__ float g_x[ELEMS];
__device__ float g_h[ELEMS];
__device__ float g_h2[ELEMS];       // tf32 shadow of g_x
__device__ float g_y[ELEMS];
__device__ float g_qkv[3*ELEMS];
__device__ float g_a3[65536];
__device__ float g_a3b[65536];
__device__ float g_wt[589824];      // conv weights, packed tile layout
__device__ float g_wq2[196608];
__device__ float g_wo2[65536];
__device__ float g_wq3[196608];
__device__ float g_wo3[65536];
__device__ float g_wq4[196608];
__device__ float g_wo4[65536];

// ---------------- tf32 helpers ----------------
__device__ __forceinline__ uint32_t f2tf(float x) {
    uint32_t r; asm("cvt.rna.tf32.f32 %0, %1;" : "=r"(r) : "f"(x)); return r;
}
__device__ __forceinline__ float tf32r(float x) { return __uint_as_float(f2tf(x)); }
__device__ __forceinline__ void mma8(float* d, const uint32_t* a, const uint32_t* b) {
    asm volatile("mma.sync.aligned.m16n8k8.row.col.f32.tf32.tf32.f32 "
        "{%0,%1,%2,%3}, {%4,%5,%6,%7}, {%8,%9}, {%0,%1,%2,%3};"
        : "+f"(d[0]), "+f"(d[1]), "+f"(d[2]), "+f"(d[3])
        : "r"(a[0]), "r"(a[1]), "r"(a[2]), "r"(a[3]), "r"(b[0]), "r"(b[1]));
}
__device__ __forceinline__ void cpa16(uint32_t dst, const void* src, int sz) {
    asm volatile("cp.async.cg.shared.global [%0], [%1], 16, %2;" :: "r"(dst), "l"(src), "r"(sz));
}
__device__ __forceinline__ void cpa_commit() { asm volatile("cp.async.commit_group;"); }
__device__ __forceinline__ void cpa_wait0()  { asm volatile("cp.async.wait_group 0;"); }

// smem stage (words): A[128][36] at 0; B packed rows [128 cols][40] at 4608. stage = 9728 words.
#define STAGE_W 9728
#define BS_OFF  4608

// packed-pos -> local k within 32-tile: pos = 8*ks + 2*tig + b  ->  k_local = 8*ks + tig + 4*b
__device__ __forceinline__ int kOfPos(int pos) {
    int ks = pos >> 3, rem = pos & 7;
    return ks*8 + (rem >> 1) + 4*(rem & 1);
}

// ---------------- transposes ----------------
__global__ void k_nchw_to_nhwc(const float* __restrict__ in, float* __restrict__ out) {
    __shared__ float tile[32][33];
    int bfq = blockIdx.z, b = bfq >> 6, fq = bfq & 63;
    int t0 = blockIdx.x * 32, c0 = blockIdx.y * 32;
    for (int r = threadIdx.y; r < 32; r += 8)
        tile[r][threadIdx.x] = in[(((size_t)b*256 + c0 + r)*64 + fq)*256 + t0 + threadIdx.x];
    __syncthreads();
    for (int r = threadIdx.y; r < 32; r += 8)
        out[((size_t)bfq*256 + t0 + r)*256 + c0 + threadIdx.x] = tile[threadIdx.x][r];
}

__global__ void k_nhwc_to_nchw_add(const float* __restrict__ xa, const float* __restrict__ xb,
                                   float* __restrict__ out) {
    __shared__ float tile[32][33];
    int bfq = blockIdx.z, b = bfq >> 6, fq = bfq & 63;
    int t0 = blockIdx.x * 32, c0 = blockIdx.y * 32;
    for (int r = threadIdx.y; r < 32; r += 8) {
        size_t p = ((size_t)bfq*256 + t0 + r)*256 + c0 + threadIdx.x;
        tile[r][threadIdx.x] = xa[p] + xb[p];
    }
    __syncthreads();
    for (int r = threadIdx.y; r < 32; r += 8)
        out[(((size_t)b*256 + c0 + r)*64 + fq)*256 + t0 + threadIdx.x] = tile[threadIdx.x][r];
}

// ---------------- weight prepack: linear W[K][N] -> P[(kt*N + n)*32 + pos] (tf32) --------
__global__ void k_prepb(const float* __restrict__ W, float* __restrict__ P, int K, int N) {
    int idx = blockIdx.x * 256 + threadIdx.x;
    if (idx >= K * N) return;
    int pos = idx & 31;
    int rest = idx >> 5;
    int n = rest % N;
    int kt = rest / N;
    int k = kt * 32 + kOfPos(pos);
    P[idx] = tf32r(W[(size_t)k * N + n]);
}

// conv weight prepack: w OIHW [co][ci][3][3]; gemm-k = kyx*256+ci.
// P[(kt*256 + co)*32 + pos] = tf32(w[co*2304 + ci*9 + kyx]) with k = kt*32 + kOfPos(pos)
__global__ void k_prepconv(const float* __restrict__ w, float* __restrict__ P) {
    int idx = blockIdx.x * 256 + threadIdx.x;   // grid 2304 -> 589824
    int pos = idx & 31;
    int rest = idx >> 5;
    int co = rest & 255;
    int kt = rest >> 8;
    int k = kt * 32 + kOfPos(pos);
    int kyx = k >> 8, ci = k & 255;
    P[idx] = tf32r(w[(size_t)co * 2304 + ci * 9 + kyx]);
}

// ---------------- GroupNorm per (b, g); ROUND -> output tf32-rounded ----------------
template<bool ROUND>
__global__ void k_gn_bg(const float* __restrict__ in, float* __restrict__ out, float eps) {
    __shared__ float rs[64];
    int b = blockIdx.x >> 5, g = blockIdx.x & 31;
    const float* base = in  + (size_t)b*16384*256 + g*8;
    float*       ob   = out + (size_t)b*16384*256 + g*8;
    float s = 0.f, s2 = 0.f;
    for (int i = threadIdx.x; i < 16384; i += 256) {
        const float4* r = (const float4*)(base + (size_t)i*256);
        float4 a = r[0], c = r[1];
        s  += a.x+a.y+a.z+a.w + c.x+c.y+c.z+c.w;
        s2 += a.x*a.x+a.y*a.y+a.z*a.z+a.w*a.w + c.x*c.x+c.y*c.y+c.z*c.z+c.w*c.w;
    }
    int lane = threadIdx.x & 31, w = threadIdx.x >> 5;
    #pragma unroll
    for (int o = 16; o; o >>= 1) {
        s  += __shfl_down_sync(0xffffffffu, s,  o);
        s2 += __shfl_down_sync(0xffffffffu, s2, o);
    }
    if (lane == 0) { rs[w] = s; rs[32 + w] = s2; }
    __syncthreads();
    if (threadIdx.x == 0) {
        float S = 0.f, S2 = 0.f;
        for (int i = 0; i < 8; i++) { S += rs[i]; S2 += rs[32 + i]; }
        rs[0] = S; rs[32] = S2;
    }
    __syncthreads();
    float mean = rs[0] * (1.f/131072.f);
    float var  = rs[32] * (1.f/131072.f) - mean*mean;
    float inv  = rsqrtf(var + eps);
    for (int i = threadIdx.x; i < 16384; i += 256) {
        const float4* r = (const float4*)(base + (size_t)i*256);
        float4 a = r[0], c = r[1];
        a.x = (a.x-mean)*inv; a.y = (a.y-mean)*inv; a.z = (a.z-mean)*inv; a.w = (a.w-mean)*inv;
        c.x = (c.x-mean)*inv; c.y = (c.y-mean)*inv; c.z = (c.z-mean)*inv; c.w = (c.w-mean)*inv;
        if (ROUND) {
            a.x = tf32r(a.x); a.y = tf32r(a.y); a.z = tf32r(a.z); a.w = tf32r(a.w);
            c.x = tf32r(c.x); c.y = tf32r(c.y); c.z = tf32r(c.z); c.w = tf32r(c.w);
        }
        float4* o4 = (float4*)(ob + (size_t)i*256);
        o4[0] = a; o4[1] = c;
    }
}

// ============ pipelined tf32 GEMM: cp.async 2-stage, 128x128 tile, Kt=32 ============
// A fp32-valued-tf32 row-major [M][K]; B PREPACKED via k_prepb.
template<bool BIAS>
__global__ __launch_bounds__(256, 2) void k_pgemm(
    const float* __restrict__ A, const float* __restrict__ Bp,
    const float* __restrict__ bias, float* __restrict__ C,
    int M, int N, int K) {
    extern __shared__ uint32_t dynsm[];
    uint32_t sbase = (uint32_t)__cvta_generic_to_shared(dynsm);
    int tid = threadIdx.x, lane = tid & 31, wid = tid >> 5;
    int g = lane >> 2, tig = lane & 3;
    int wm = wid >> 1, wn = wid & 1;
    int bn = blockIdx.x * 128, bm = blockIdx.y * 128;
    float acc[2][8][4] = {};
    int KT = K >> 5;

    auto copy = [&](int kt, int s) {
        int k0 = kt << 5;
        #pragma unroll
        for (int i = 0; i < 4; i++) {
            int idx = tid + i*256;
            int row = idx >> 3, c4 = idx & 7;
            cpa16(sbase + (s*STAGE_W + row*36 + c4*4)*4,
                  A + (size_t)(bm + row)*K + k0 + c4*4, 16);
            cpa16(sbase + (s*STAGE_W + BS_OFF + row*40 + c4*4)*4,
                  Bp + ((size_t)kt*N + bn + row)*32 + c4*4, 16);
        }
        cpa_commit();
    };

    copy(0, 0);
    for (int kt = 0; kt < KT; kt++) {
        cpa_wait0();
        __syncthreads();
        if (kt + 1 < KT) copy(kt + 1, (kt + 1) & 1);
        const uint32_t* As = dynsm + (kt & 1)*STAGE_W;
        const uint32_t* Bt = As + BS_OFF;
        #pragma unroll
        for (int ks = 0; ks < 4; ks++) {
            int k = ks * 8;
            uint32_t af[2][4], bf[8][2];
            #pragma unroll
            for (int mt = 0; mt < 2; mt++) {
                int r0 = wm*32 + mt*16;
                af[mt][0] = As[(r0 + g)*36 + k + tig];
                af[mt][1] = As[(r0 + g + 8)*36 + k + tig];
                af[mt][2] = As[(r0 + g)*36 + k + tig + 4];
                af[mt][3] = As[(r0 + g + 8)*36 + k + tig + 4];
            }
            #pragma unroll
            for (int nt = 0; nt < 8; nt++) {
                int c0 = wn*64 + nt*8 + g;
                uint2 bv = *(const uint2*)&Bt[c0*40 + k + tig*2];   // k = 8*ks
                bf[nt][0] = bv.x; bf[nt][1] = bv.y;
            }
            #pragma unroll
            for (int mt = 0; mt < 2; mt++)
                #pragma unroll
                for (int nt = 0; nt < 8; nt++)
                    mma8(acc[mt][nt], af[mt], bf[nt]);
        }
    }
    #pragma unroll
    for (int mt = 0; mt < 2; mt++) {
        int row = bm + wm*32 + mt*16 + g;
        #pragma unroll
        for (int nt = 0; nt < 8; nt++) {
            int col = bn + wn*64 + nt*8 + tig*2;
            float2 v0 = make_float2(acc[mt][nt][0], acc[mt][nt][1]);
            float2 v1 = make_float2(acc[mt][nt][2], acc[mt][nt][3]);
            if (BIAS) {
                float b0 = bias[col], b1v = bias[col + 1];
                v0.x += b0; v0.y += b1v; v1.x += b0; v1.y += b1v;
            }
            *(float2*)(C + (size_t)row*N + col) = v0;
            *(float2*)(C + (size_t)(row + 8)*N + col) = v1;
        }
    }
}

// ============ pipelined conv3x3 implicit GEMM, prepacked weights ============
template<int MODE>
__global__ __launch_bounds__(256, 2) void k_pconv(
    const float* __restrict__ In, const float* __restrict__ Wp,
    const float* __restrict__ bias, const float* __restrict__ temb,
    const float* __restrict__ gate, float* __restrict__ Out) {
    extern __shared__ uint32_t dynsm[];
    uint32_t sbase = (uint32_t)__cvta_generic_to_shared(dynsm);
    int tid = threadIdx.x, lane = tid & 31, wid = tid >> 5;
    int g = lane >> 2, tig = lane & 3;
    int wm = wid >> 1, wn = wid & 1;
    int bn = blockIdx.x * 128, bm = blockIdx.y * 128;
    float acc[2][8][4] = {};

    int pb[4], pfy[4], pfx[4];
    #pragma unroll
    for (int i = 0; i < 4; i++) {
        int p = bm + ((tid + i*256) >> 3);
        pb[i] = p >> 14; pfy[i] = (p >> 8) & 63; pfx[i] = p & 255;
    }

    auto copy = [&](int kt, int s) {
        int k0 = kt << 5;
        int kyx = k0 >> 8, ci0 = k0 & 255;
        int ky = kyx / 3, kx = kyx - ky*3;
        #pragma unroll
        for (int i = 0; i < 4; i++) {
            int idx = tid + i*256;
            int row = idx >> 3, c4 = idx & 7;
            int fy2 = pfy[i] + ky - 1, fx2 = pfx[i] + kx - 1;
            bool v = ((unsigned)fy2 < 64u) && ((unsigned)fx2 < 256u);
            int fy2c = v ? fy2 : 0, fx2c = v ? fx2 : 0;
            cpa16(sbase + (s*STAGE_W + row*36 + c4*4)*4,
                  In + (((size_t)(pb[i]*64 + fy2c))*256 + fx2c)*256 + ci0 + c4*4,
                  v ? 16 : 0);
            cpa16(sbase + (s*STAGE_W + BS_OFF + row*40 + c4*4)*4,
                  Wp + ((size_t)kt*256 + bn + row)*32 + c4*4, 16);
        }
        cpa_commit();
    };

    copy(0, 0);
    for (int kt = 0; kt < 72; kt++) {
        cpa_wait0();
        __syncthreads();
        if (kt + 1 < 72) copy(kt + 1, (kt + 1) & 1);
        const uint32_t* As = dynsm + (kt & 1)*STAGE_W;
        const uint32_t* Bt = As + BS_OFF;
        #pragma unroll
        for (int ks = 0; ks < 4; ks++) {
            int k = ks * 8;
            uint32_t af[2][4], bf[8][2];
            #pragma unroll
            for (int mt = 0; mt < 2; mt++) {
                int r0 = wm*32 + mt*16;
                af[mt][0] = As[(r0 + g)*36 + k + tig];
                af[mt][1] = As[(r0 + g + 8)*36 + k + tig];
                af[mt][2] = As[(r0 + g)*36 + k + tig + 4];
                af[mt][3] = As[(r0 + g + 8)*36 + k + tig + 4];
            }
            #pragma unroll
            for (int nt = 0; nt < 8; nt++) {
                int c0 = wn*64 + nt*8 + g;
                uint2 bv = *(const uint2*)&Bt[c0*40 + k + tig*2];
                bf[nt][0] = bv.x; bf[nt][1] = bv.y;
            }
            #pragma unroll
            for (int mt = 0; mt < 2; mt++)
                #pragma unroll
                for (int nt = 0; nt < 8; nt++)
                    mma8(acc[mt][nt], af[mt], bf[nt]);
        }
    }
    float gd = (MODE == 1) ? gate[0] : 0.f;
    #pragma unroll
    for (int mt = 0; mt < 2; mt++) {
        int row = bm + wm*32 + mt*16 + g;
        int bidx = row >> 14;
        #pragma unroll
        for (int nt = 0; nt < 8; nt++) {
            int col = bn + wn*64 + nt*8 + tig*2;
            float v[4] = {acc[mt][nt][0], acc[mt][nt][1], acc[mt][nt][2], acc[mt][nt][3]};
            if (MODE == 1) {
                float a0 = bias[col]     + gd * temb[bidx*256 + col];
                float a1 = bias[col + 1] + gd * temb[bidx*256 + col + 1];
                v[0] += a0; v[1] += a1; v[2] += a0; v[3] += a1;
                #pragma unroll
                for (int j = 0; j < 4; j++) v[j] = v[j] / (1.f + __expf(-v[j]));
            }
            *(float2*)(Out + (size_t)row*256 + col) = make_float2(v[0], v[1]);
            *(float2*)(Out + (size_t)(row + 8)*256 + col) = make_float2(v[2], v[3]);
        }
    }
}

// ---------------- x += gate*h; also write tf32 shadow of new x ----------------
__global__ void k_axpy_gate(float* __restrict__ x, const float* __restrict__ h,
                            const float* __restrict__ gate, float* __restrict__ xs) {
    size_t i = ((size_t)blockIdx.x * 256 + threadIdx.x) * 4;
    float g = gate[0];
    float4 xv = *(float4*)(x + i);
    float4 hv = *(const float4*)(h + i);
    xv.x += g*hv.x; xv.y += g*hv.y; xv.z += g*hv.z; xv.w += g*hv.w;
    *(float4*)(x + i) = xv;
    float4 sv = make_float4(tf32r(xv.x), tf32r(xv.y), tf32r(xv.z), tf32r(xv.w));
    *(float4*)(xs + i) = sv;
}

// ---------------- layer2 attention over Fq per (b,t,h); output tf32-rounded ----------
__global__ void k_attn_freq(const float* __restrict__ qkv, float* __restrict__ y) {
    __shared__ float q[64][33], kk[64][33], v[64][33];
    __shared__ float S[64][65];
    int bt = blockIdx.x, h = blockIdx.y;
    int b = bt >> 8, t = bt & 255;
    int tid = threadIdx.x;
    for (int i = tid; i < 2048; i += 128) {
        int fq = i >> 5, d = i & 31;
        size_t base = ((size_t)((b*64 + fq)*256 + t))*768 + h*32 + d;
        q[fq][d]  = qkv[base];
        kk[fq][d] = qkv[base + 256];
        v[fq][d]  = qkv[base + 512];
    }
    __syncthreads();
    const float scale = 0.17677669529663687f;
    for (int i = tid; i < 4096; i += 128) {
        int L = i >> 6, l = i & 63;
        float s = 0.f;
        #pragma unroll
        for (int d = 0; d < 32; d++) s += q[L][d] * kk[l][d];
        S[L][l] = s * scale;
    }
    __syncthreads();
    if (tid < 64) {
        float m = -1e30f;
        for (int l = 0; l < 64; l++) m = fmaxf(m, S[tid][l]);
        float su = 0.f;
        for (int l = 0; l < 64; l++) { float e = __expf(S[tid][l] - m); S[tid][l] = e; su += e; }
        float r = 1.f / su;
        for (int l = 0; l < 64; l++) S[tid][l] *= r;
    }
    __syncthreads();
    for (int i = tid; i < 2048; i += 128) {
        int L = i >> 5, d = i & 31;
        float s = 0.f;
        #pragma unroll
        for (int l = 0; l < 64; l++) s += S[L][l] * v[l][d];
        y[((size_t)((b*64 + L)*256 + t))*256 + h*32 + d] = tf32r(s);
    }
}

// ---------------- per-token GN then x += g2*y; write tf32 shadow of new x ----------
__global__ void k_gnrow_add(const float* __restrict__ yv, float* __restrict__ x,
                            const float* __restrict__ gate, float* __restrict__ xs) {
    int idx = blockIdx.x * 256 + threadIdx.x;
    int p = idx >> 5, g = idx & 31;
    size_t off = (size_t)p * 256 + g * 8;
    float4 a = *(const float4*)(yv + off), c = *(const float4*)(yv + off + 4);
    float vals[8] = {a.x, a.y, a.z, a.w, c.x, c.y, c.z, c.w};
    float m = 0.f;
    #pragma unroll
    for (int j = 0; j < 8; j++) m += vals[j];
    m *= 0.125f;
    float var = 0.f;
    #pragma unroll
    for (int j = 0; j < 8; j++) { float dd = vals[j] - m; var += dd * dd; }
    var *= 0.125f;
    float inv = rsqrtf(var + 1e-5f);
    float gg = gate[0];
    float xo[8];
    float4 xa = *(float4*)(x + off), xb = *(float4*)(x + off + 4);
    xo[0]=xa.x; xo[1]=xa.y; xo[2]=xa.z; xo[3]=xa.w;
    xo[4]=xb.x; xo[5]=xb.y; xo[6]=xb.z; xo[7]=xb.w;
    #pragma unroll
    for (int j = 0; j < 8; j++) xo[j] += gg * (vals[j] - m) * inv;
    *(float4*)(x + off)     = make_float4(xo[0], xo[1], xo[2], xo[3]);
    *(float4*)(x + off + 4) = make_float4(xo[4], xo[5], xo[6], xo[7]);
    *(float4*)(xs + off)     = make_float4(tf32r(xo[0]), tf32r(xo[1]), tf32r(xo[2]), tf32r(xo[3]));
    *(float4*)(xs + off + 4) = make_float4(tf32r(xo[4]), tf32r(xo[5]), tf32r(xo[6]), tf32r(xo[7]));
}

// ---------------- layer3 global attention per (bfq, h); output tf32-rounded --------
__global__ void k_attn_time(const float* __restrict__ qkv, float* __restrict__ yout) {
    __shared__ float part[8][32];
    __shared__ float qm[32];
    __shared__ float prob[256];
    __shared__ float redm[8], reds[8];
    int bfq = blockIdx.x, h = blockIdx.y;
    int tid = threadIdx.x;
    size_t tokbase = (size_t)bfq * 256;
    int d = tid & 31, grp = tid >> 5;
    float s = 0.f;
    for (int t = grp; t < 256; t += 8)
        s += qkv[(tokbase + t)*768 + h*32 + d];
    part[grp][d] = s;
    __syncthreads();
    if (tid < 32) {
        float ss = 0.f;
        #pragma unroll
        for (int g = 0; g < 8; g++) ss += part[g][tid];
        qm[tid] = ss * (1.f/256.f);
    }
    __syncthreads();
    const float* kr = qkv + (tokbase + tid)*768 + 256 + h*32;
    float sc = 0.f;
    #pragma unroll
    for (int dd = 0; dd < 32; dd++) sc += qm[dd] * kr[dd];
    sc *= 0.17677669529663687f;
    float m = sc;
    #pragma unroll
    for (int o = 16; o; o >>= 1) m = fmaxf(m, __shfl_xor_sync(0xffffffffu, m, o));
    if ((tid & 31) == 0) redm[grp] = m;
    __syncthreads();
    float M = redm[0];
    #pragma unroll
    for (int g = 1; g < 8; g++) M = fmaxf(M, redm[g]);
    float e = __expf(sc - M);
    float su = e;
    #pragma unroll
    for (int o = 16; o; o >>= 1) su += __shfl_xor_sync(0xffffffffu, su, o);
    if ((tid & 31) == 0) reds[grp] = su;
    __syncthreads();
    float Ssum = 0.f;
    #pragma unroll
    for (int g = 0; g < 8; g++) Ssum += reds[g];
    prob[tid] = e / Ssum;
    __syncthreads();
    float acc = 0.f;
    for (int t = grp; t < 256; t += 8)
        acc += prob[t] * qkv[(tokbase + t)*768 + 512 + h*32 + d];
    part[grp][d] = acc;
    __syncthreads();
    if (tid < 32) {
        float ss = 0.f;
        #pragma unroll
        for (int g = 0; g < 8; g++) ss += part[g][tid];
        yout[(size_t)bfq*256 + h*32 + tid] = tf32r(ss);
    }
}

// ---------------- layer3 epilogue ----------------
__global__ void k_gn_bcast_add(const float* __restrict__ yv, float* __restrict__ x,
                               const float* __restrict__ gate) {
    __shared__ float yn[256];
    int bfq = blockIdx.x, tid = threadIdx.x;
    if (tid < 32) {
        const float* r = yv + bfq*256 + tid*8;
        float vals[8];
        #pragma unroll
        for (int j = 0; j < 8; j++) vals[j] = r[j];
        float m = 0.f;
        #pragma unroll
        for (int j = 0; j < 8; j++) m += vals[j];
        m *= 0.125f;
        float var = 0.f;
        #pragma unroll
        for (int j = 0; j < 8; j++) { float dd = vals[j] - m; var += dd * dd; }
        var *= 0.125f;
        float inv = rsqrtf(var + 1e-5f);
        #pragma unroll
        for (int j = 0; j < 8; j++) yn[tid*8 + j] = (vals[j] - m) * inv;
    }
    __syncthreads();
    float add = gate[0] * yn[tid];
    float* xp = x + (size_t)bfq * 65536 + tid;
    for (int t = 0; t < 256; t++) xp[(size_t)t * 256] += add;
}

// ---------------- layer4 LSA; output tf32-rounded ----------------
__global__ void k_attn_lsa(const float* __restrict__ qkv, float* __restrict__ y) {
    __shared__ float q[16][33], kk[16][33], v[16][33];
    __shared__ float S[16][17];
    int blk = blockIdx.x;
    size_t p0 = (size_t)(blk >> 4) * 256 + (blk & 15) * 16;
    int tid = threadIdx.x;
    int qi = tid >> 4, kj = tid & 15;
    const float scale = 0.17677669529663687f;
    for (int h = 0; h < 8; h++) {
        for (int i = tid; i < 512; i += 256) {
            int r = i >> 5, d = i & 31;
            size_t a = (p0 + r)*768 + h*32 + d;
            q[r][d] = qkv[a]; kk[r][d] = qkv[a + 256]; v[r][d] = qkv[a + 512];
        }
        __syncthreads();
        float s = 0.f;
        #pragma unroll
        for (int d = 0; d < 32; d++) s += q[qi][d] * kk[kj][d];
        S[qi][kj] = s * scale;
        __syncthreads();
        if (tid < 16) {
            float m = -1e30f;
            for (int j = 0; j < 16; j++) m = fmaxf(m, S[tid][j]);
            float su = 0.f;
            for (int j = 0; j < 16; j++) { float e = __expf(S[tid][j] - m); S[tid][j] = e; su += e; }
            float r = 1.f / su;
            for (int j = 0; j < 16; j++) S[tid][j] *= r;
        }
        __syncthreads();
        for (int i = tid; i < 512; i += 256) {
            int r = i >> 5, d = i & 31;
            float s2 = 0.f;
            #pragma unroll
            for (int j = 0; j < 16; j++) s2 += S[r][j] * v[j][d];
            y[(p0 + r)*256 + h*32 + d] = tf32r(s2);
        }
        __syncthreads();
    }
}

// =====================================================================================
extern "C" void kernel_launch(void* const* d_in, const int* in_sizes, int n_in,
                              void* d_out, int out_size) {
    const float* x     = (const float*)d_in[0];
    const float* temb  = (const float*)d_in[1];
    const float* w1    = (const float*)d_in[2];
    const float* b1    = (const float*)d_in[3];
    const float* w2    = (const float*)d_in[4];
    const float* gdiff = (const float*)d_in[5];
    const float* gres  = (const float*)d_in[6];
    const float* g2    = (const float*)d_in[7];
    const float* g3    = (const float*)d_in[8];
    const float* qkv2w = (const float*)d_in[9];
    const float* qkv2b = (const float*)d_in[10];
    const float* out2w = (const float*)d_in[11];
    const float* qkv3w = (const float*)d_in[12];
    const float* qkv3b = (const float*)d_in[13];
    const float* out3w = (const float*)d_in[14];
    const float* lsaqw = (const float*)d_in[15];
    const float* lsaow = (const float*)d_in[16];
    float* out = (float*)d_out;

    float *px, *ph, *ph2, *py, *pqkv, *pa3, *pa3b, *pwt;
    float *pwq2, *pwo2, *pwq3, *pwo3, *pwq4, *pwo4;
    cudaGetSymbolAddress((void**)&px,   g_x);
    cudaGetSymbolAddress((void**)&ph,   g_h);
    cudaGetSymbolAddress((void**)&ph2,  g_h2);
    cudaGetSymbolAddress((void**)&py,   g_y);
    cudaGetSymbolAddress((void**)&pqkv, g_qkv);
    cudaGetSymbolAddress((void**)&pa3,  g_a3);
    cudaGetSymbolAddress((void**)&pa3b, g_a3b);
    cudaGetSymbolAddress((void**)&pwt,  g_wt);
    cudaGetSymbolAddress((void**)&pwq2, g_wq2);
    cudaGetSymbolAddress((void**)&pwo2, g_wo2);
    cudaGetSymbolAddress((void**)&pwq3, g_wq3);
    cudaGetSymbolAddress((void**)&pwo3, g_wo3);
    cudaGetSymbolAddress((void**)&pwq4, g_wq4);
    cudaGetSymbolAddress((void**)&pwo4, g_wo4);

    const int SMEM = 2 * STAGE_W * 4;   // 77824 B
    cudaFuncSetAttribute(k_pgemm<true>,  cudaFuncAttributeMaxDynamicSharedMemorySize, SMEM);
    cudaFuncSetAttribute(k_pgemm<false>, cudaFuncAttributeMaxDynamicSharedMemorySize, SMEM);
    cudaFuncSetAttribute(k_pconv<0>,     cudaFuncAttributeMaxDynamicSharedMemorySize, SMEM);
    cudaFuncSetAttribute(k_pconv<1>,     cudaFuncAttributeMaxDynamicSharedMemorySize, SMEM);

    dim3 tb32(32, 8);

    k_nchw_to_nhwc<<<dim3(8, 8, 256), tb32>>>(x, px);

    // weight prepack (tf32, tile-packed)
    k_prepb<<<768, 256>>>(qkv2w, pwq2, 256, 768);
    k_prepb<<<256, 256>>>(out2w, pwo2, 256, 256);
    k_prepb<<<768, 256>>>(qkv3w, pwq3, 256, 768);
    k_prepb<<<256, 256>>>(out3w, pwo3, 256, 256);
    k_prepb<<<768, 256>>>(lsaqw, pwq4, 256, 768);
    k_prepb<<<256, 256>>>(lsaow, pwo4, 256, 256);

    // ---- Residual block ----
    k_gn_bg<true><<<128, 256>>>(px, ph, 1e-6f);
    k_prepconv<<<2304, 256>>>(w1, pwt);
    k_pconv<1><<<dim3(2, 512), 256, SMEM>>>(ph, pwt, b1, temb, gdiff, ph2);
    k_gn_bg<true><<<128, 256>>>(ph2, ph, 1e-6f);
    k_prepconv<<<2304, 256>>>(w2, pwt);
    k_pconv<0><<<dim3(2, 512), 256, SMEM>>>(ph, pwt, nullptr, nullptr, nullptr, ph2);
    k_gn_bg<false><<<128, 256>>>(ph2, ph, 1e-6f);
    k_axpy_gate<<<16384, 256>>>(px, ph, gres, ph2);   // ph2 = tf32 shadow of px

    // ---- layer2 ----
    k_pgemm<true><<<dim3(6, 512), 256, SMEM>>>(ph2, pwq2, qkv2b, pqkv, NTOK, 768, 256);
    k_attn_freq<<<dim3(1024, 8), 128>>>(pqkv, py);
    k_pgemm<false><<<dim3(2, 512), 256, SMEM>>>(py, pwo2, nullptr, ph, NTOK, 256, 256);
    k_gnrow_add<<<8192, 256>>>(ph, px, g2, ph2);      // update px + refresh shadow

    // ---- layer3 ----
    k_pgemm<true><<<dim3(6, 512), 256, SMEM>>>(ph2, pwq3, qkv3b, pqkv, NTOK, 768, 256);
    k_attn_time<<<dim3(256, 8), 256>>>(pqkv, pa3);
    k_pgemm<false><<<dim3(2, 2), 256, SMEM>>>(pa3, pwo3, nullptr, pa3b, 256, 256, 256);
    k_gn_bcast_add<<<256, 256>>>(pa3b, px, g3);

    // ---- layer4 ----
    k_gn_bg<true><<<128, 256>>>(px, ph, 1e-5f);
    k_pgemm<false><<<dim3(6, 512), 256, SMEM>>>(ph, pwq4, nullptr, pqkv, NTOK, 768, 256);
    k_attn_lsa<<<4096, 256>>>(pqkv, py);
    k_pgemm<false><<<dim3(2, 512), 256, SMEM>>>(py, pwo4, nullptr, ph, NTOK, 256, 256);

    k_nhwc_to_nchw_add<<<dim3(8, 8, 256), tb32>>>(px, ph, out);
}